// round 4
// baseline (speedup 1.0000x reference)
#include <cuda_runtime.h>
#include <math.h>

#define BB 256
#define NT 128
#define TD 64
#define HH 8
#define DH 64
#define IN 512
#define MM 266
#define ES 272          /* padded feature stride for E matrices */
#define FH 256

#define DN    0.35355339059327373f   /* 64^-0.25 */
#define RATIO 0.0613139076f          /* 266^-0.5 */
#define RE    6.13139076e-6f         /* RATIO * 1e-4 */

__device__ float g_q[BB*HH*NT*DH];
__device__ float g_k[BB*HH*NT*DH];
__device__ float g_v[BB*HH*NT*DH];
__device__ float g_Ek[BB*HH*NT*ES];
__device__ float g_Eq[BB*HH*NT*ES];
__device__ float g_ctxU[BB*HH*MM*DH];
__device__ float g_ksumU[BB*HH*MM];
__device__ float g_vsum[BB*HH*DH];
__device__ float g_qdg[BB*HH*NT];
__device__ float g_Tn[BB*HH*NT];
__device__ float g_Emx[BB*HH*NT];
__device__ float g_csA[BB*HH*DH];
__device__ float g_kss[BB*HH];
__device__ float g_o[BB*NT*IN];
__device__ float g_t[BB*NT*TD];
__device__ unsigned g_kmax;

__device__ __forceinline__ unsigned enc_f(float f) {
    unsigned u = __float_as_uint(f);
    return (u & 0x80000000u) ? ~u : (u | 0x80000000u);
}
__device__ __forceinline__ float dec_f(unsigned k) {
    return (k & 0x80000000u) ? __uint_as_float(k & 0x7fffffffu)
                             : __uint_as_float(~k);
}

__global__ void k_init() { g_kmax = 0u; }

// ---------------- K1: LN1 + QKV projection ----------------
__global__ __launch_bounds__(512, 1)
void k1_ln_qkv(const float* __restrict__ x,
               const float* __restrict__ g1, const float* __restrict__ b1,
               const float* __restrict__ Wq, const float* __restrict__ bq,
               const float* __restrict__ Wk, const float* __restrict__ bk,
               const float* __restrict__ Wv, const float* __restrict__ bv)
{
    __shared__ float hsm[NT*65];
    int b = blockIdx.x, tid = threadIdx.x;
    const float* xb = x + (size_t)b*NT*TD;
    for (int i = tid; i < NT*TD; i += 512)
        hsm[(i >> 6)*65 + (i & 63)] = xb[i];
    __syncthreads();
    if (tid < NT) {
        float* r = &hsm[tid*65];
        float mu = 0.f;
#pragma unroll
        for (int d = 0; d < 64; d++) mu += r[d];
        mu *= (1.f/64.f);
        float var = 0.f;
#pragma unroll
        for (int d = 0; d < 64; d++) { float t = r[d]-mu; var += t*t; }
        var *= (1.f/64.f);
        float inv = rsqrtf(var + 1e-5f);
#pragma unroll
        for (int d = 0; d < 64; d++) r[d] = (r[d]-mu)*inv*g1[d] + b1[d];
    }
    __syncthreads();

    int jt = tid & 127, ng = tid >> 7;
    int j4 = jt*4;
    int head = j4 >> 6, doff = j4 & 63;

#define PROJ_PASS(W, bias, dst_arr)                                         \
    {                                                                       \
        float4 bb4 = *(const float4*)((bias) + j4);                         \
        for (int it = 0; it < 32; ++it) {                                   \
            int n = it*4 + ng;                                              \
            float4 a = bb4;                                                 \
            _Pragma("unroll")                                               \
            for (int d = 0; d < 64; ++d) {                                  \
                float hv = hsm[n*65 + d];                                   \
                float4 w = *(const float4*)((W) + d*IN + j4);               \
                a.x = fmaf(hv, w.x, a.x); a.y = fmaf(hv, w.y, a.y);         \
                a.z = fmaf(hv, w.z, a.z); a.w = fmaf(hv, w.w, a.w);         \
            }                                                               \
            int dst = ((b*HH + head)*NT + n)*DH + doff;                     \
            *(float4*)((dst_arr) + dst) = a;                                \
        }                                                                   \
    }
    PROJ_PASS(Wq, bq, g_q)
    PROJ_PASS(Wk, bk, g_k)
    PROJ_PASS(Wv, bv, g_v)
#undef PROJ_PASS
}

// ---------------- kAa: E = exp(X.P^T [- diag]) feature kernels ----------------
#define FT 160

// keys: Ek[n][m] = exp(k^.p - diag_k[n]); track global max of dd
__global__ __launch_bounds__(FT, 2)
void k2a_feat(const float* __restrict__ proj)
{
    __shared__ float ks[NT*DH];
    __shared__ float diag[NT];
    __shared__ unsigned smax;
    int bh = blockIdx.x, t = threadIdx.x;
    if (t == 0) smax = 0u;
    const float* kg = g_k + (size_t)bh*NT*DH;
    for (int i = t; i < NT*DH; i += FT) ks[i] = kg[i] * DN;
    __syncthreads();
    if (t < NT) {
        float s = 0.f;
#pragma unroll
        for (int d = 0; d < 64; d++) { float v = ks[t*64+d]; s += v*v; }
        diag[t] = 0.5f * s;
    }
    __syncthreads();

    int mA = t, mB = t + FT;
    bool aB = (mB < MM), wB = (mB < ES);
    float pa[64], pb[64];
#pragma unroll
    for (int j = 0; j < 16; ++j) {
        float4 p4 = *(const float4*)(proj + mA*64 + 4*j);
        pa[4*j]=p4.x; pa[4*j+1]=p4.y; pa[4*j+2]=p4.z; pa[4*j+3]=p4.w;
    }
    if (aB) {
#pragma unroll
        for (int j = 0; j < 16; ++j) {
            float4 p4 = *(const float4*)(proj + mB*64 + 4*j);
            pb[4*j]=p4.x; pb[4*j+1]=p4.y; pb[4*j+2]=p4.z; pb[4*j+3]=p4.w;
        }
    } else {
#pragma unroll
        for (int j = 0; j < 64; ++j) pb[j] = 0.f;
    }

    float* Eb = g_Ek + (size_t)bh*NT*ES;
    float dmax = -1e30f;
    for (int n = 0; n < NT; ++n) {
        const float4* kr = (const float4*)(ks + n*64);
        float a0=0.f,a1=0.f,a2=0.f,a3=0.f,b0=0.f,b1=0.f,b2=0.f,b3=0.f;
#pragma unroll
        for (int j = 0; j < 16; ++j) {
            float4 kk = kr[j];
            a0=fmaf(kk.x,pa[4*j  ],a0); a1=fmaf(kk.y,pa[4*j+1],a1);
            a2=fmaf(kk.z,pa[4*j+2],a2); a3=fmaf(kk.w,pa[4*j+3],a3);
            b0=fmaf(kk.x,pb[4*j  ],b0); b1=fmaf(kk.y,pb[4*j+1],b1);
            b2=fmaf(kk.z,pb[4*j+2],b2); b3=fmaf(kk.w,pb[4*j+3],b3);
        }
        float ddA = (a0+a1)+(a2+a3), ddB = (b0+b1)+(b2+b3);
        dmax = fmaxf(dmax, ddA);
        if (aB) dmax = fmaxf(dmax, ddB);
        float d = diag[n];
        Eb[n*ES + mA] = __expf(ddA - d);
        if (wB) Eb[n*ES + mB] = aB ? __expf(ddB - d) : 0.f;
    }
    unsigned key = enc_f(dmax);
#pragma unroll
    for (int o = 16; o; o >>= 1)
        key = max(key, __shfl_xor_sync(0xffffffffu, key, o));
    if ((t & 31) == 0) atomicMax(&smax, key);
    __syncthreads();
    if (t == 0) atomicMax(&g_kmax, smax);
}

// queries: Eq[n][m] = exp(q^.p); also write qdiag
__global__ __launch_bounds__(FT, 2)
void k3a_feat(const float* __restrict__ proj)
{
    __shared__ float qs[NT*DH];
    int bh = blockIdx.x, t = threadIdx.x;
    const float* qg = g_q + (size_t)bh*NT*DH;
    for (int i = t; i < NT*DH; i += FT) qs[i] = qg[i] * DN;
    __syncthreads();
    if (t < NT) {
        float s = 0.f;
#pragma unroll
        for (int d = 0; d < 64; d++) { float v = qs[t*64+d]; s += v*v; }
        g_qdg[(size_t)bh*NT + t] = 0.5f * s;
    }

    int mA = t, mB = t + FT;
    bool aB = (mB < MM), wB = (mB < ES);
    float pa[64], pb[64];
#pragma unroll
    for (int j = 0; j < 16; ++j) {
        float4 p4 = *(const float4*)(proj + mA*64 + 4*j);
        pa[4*j]=p4.x; pa[4*j+1]=p4.y; pa[4*j+2]=p4.z; pa[4*j+3]=p4.w;
    }
    if (aB) {
#pragma unroll
        for (int j = 0; j < 16; ++j) {
            float4 p4 = *(const float4*)(proj + mB*64 + 4*j);
            pb[4*j]=p4.x; pb[4*j+1]=p4.y; pb[4*j+2]=p4.z; pb[4*j+3]=p4.w;
        }
    } else {
#pragma unroll
        for (int j = 0; j < 64; ++j) pb[j] = 0.f;
    }

    float* Eb = g_Eq + (size_t)bh*NT*ES;
    for (int n = 0; n < NT; ++n) {
        const float4* qr = (const float4*)(qs + n*64);
        float a0=0.f,a1=0.f,a2=0.f,a3=0.f,b0=0.f,b1=0.f,b2=0.f,b3=0.f;
#pragma unroll
        for (int j = 0; j < 16; ++j) {
            float4 qq = qr[j];
            a0=fmaf(qq.x,pa[4*j  ],a0); a1=fmaf(qq.y,pa[4*j+1],a1);
            a2=fmaf(qq.z,pa[4*j+2],a2); a3=fmaf(qq.w,pa[4*j+3],a3);
            b0=fmaf(qq.x,pb[4*j  ],b0); b1=fmaf(qq.y,pb[4*j+1],b1);
            b2=fmaf(qq.z,pb[4*j+2],b2); b3=fmaf(qq.w,pb[4*j+3],b3);
        }
        Eb[n*ES + mA] = __expf((a0+a1)+(a2+a3));
        if (wB) Eb[n*ES + mB] = aB ? __expf((b0+b1)+(b2+b3)) : 0.f;
    }
}

// ---------------- k2b: ctxU = Ek^T @ V, ksumU, vsum ----------------
__global__ __launch_bounds__(256, 2)
void k2b_ctx()
{
    __shared__ float vs[NT*DH];
    int bh = blockIdx.x, t = threadIdx.x;
    int m0 = blockIdx.y << 7;
    const float* vg = g_v + (size_t)bh*NT*DH;
    for (int i = t; i < NT*DH; i += 256) vs[i] = vg[i];
    __syncthreads();

    int mg = t >> 3, dg = t & 7;
    int mb = m0 + mg*4, d0 = dg*8;
    if (mb < ES) {
        const float* Eb = g_Ek + (size_t)bh*NT*ES + mb;
        float acc[32], ksm[4];
#pragma unroll
        for (int j = 0; j < 32; ++j) acc[j] = 0.f;
#pragma unroll
        for (int j = 0; j < 4; ++j) ksm[j] = 0.f;

#pragma unroll 2
        for (int n = 0; n < NT; ++n) {
            const float* er = Eb + n*ES;
            float e0 = er[0], e1 = er[1], e2 = er[2], e3 = er[3];
            float4 v0 = *(const float4*)(vs + n*64 + d0);
            float4 v1 = *(const float4*)(vs + n*64 + d0 + 4);
            ksm[0]+=e0; ksm[1]+=e1; ksm[2]+=e2; ksm[3]+=e3;
            acc[ 0]=fmaf(e0,v0.x,acc[ 0]); acc[ 1]=fmaf(e0,v0.y,acc[ 1]);
            acc[ 2]=fmaf(e0,v0.z,acc[ 2]); acc[ 3]=fmaf(e0,v0.w,acc[ 3]);
            acc[ 4]=fmaf(e0,v1.x,acc[ 4]); acc[ 5]=fmaf(e0,v1.y,acc[ 5]);
            acc[ 6]=fmaf(e0,v1.z,acc[ 6]); acc[ 7]=fmaf(e0,v1.w,acc[ 7]);
            acc[ 8]=fmaf(e1,v0.x,acc[ 8]); acc[ 9]=fmaf(e1,v0.y,acc[ 9]);
            acc[10]=fmaf(e1,v0.z,acc[10]); acc[11]=fmaf(e1,v0.w,acc[11]);
            acc[12]=fmaf(e1,v1.x,acc[12]); acc[13]=fmaf(e1,v1.y,acc[13]);
            acc[14]=fmaf(e1,v1.z,acc[14]); acc[15]=fmaf(e1,v1.w,acc[15]);
            acc[16]=fmaf(e2,v0.x,acc[16]); acc[17]=fmaf(e2,v0.y,acc[17]);
            acc[18]=fmaf(e2,v0.z,acc[18]); acc[19]=fmaf(e2,v0.w,acc[19]);
            acc[20]=fmaf(e2,v1.x,acc[20]); acc[21]=fmaf(e2,v1.y,acc[21]);
            acc[22]=fmaf(e2,v1.z,acc[22]); acc[23]=fmaf(e2,v1.w,acc[23]);
            acc[24]=fmaf(e3,v0.x,acc[24]); acc[25]=fmaf(e3,v0.y,acc[25]);
            acc[26]=fmaf(e3,v0.z,acc[26]); acc[27]=fmaf(e3,v0.w,acc[27]);
            acc[28]=fmaf(e3,v1.x,acc[28]); acc[29]=fmaf(e3,v1.y,acc[29]);
            acc[30]=fmaf(e3,v1.z,acc[30]); acc[31]=fmaf(e3,v1.w,acc[31]);
        }
#pragma unroll
        for (int i = 0; i < 4; ++i) {
            int m = mb + i;
            if (m < MM) {
                float* dst = g_ctxU + ((size_t)bh*MM + m)*DH + d0;
                *(float4*)(dst)   = make_float4(acc[i*8  ],acc[i*8+1],acc[i*8+2],acc[i*8+3]);
                *(float4*)(dst+4) = make_float4(acc[i*8+4],acc[i*8+5],acc[i*8+6],acc[i*8+7]);
                if (dg == 0) g_ksumU[(size_t)bh*MM + m] = ksm[i];
            }
        }
    }
    if (blockIdx.y == 0 && t < DH) {
        float s = 0.f;
        for (int n = 0; n < NT; ++n) s += vs[n*64 + t];
        g_vsum[(size_t)bh*DH + t] = s;
    }
}

// ---------------- k3x: per-bh stats (Tn, Emx, csum, kss) ----------------
__global__ __launch_bounds__(288, 4)
void k3x_stats()
{
    __shared__ float ksm[ES];
    int bh = blockIdx.x, t = threadIdx.x;
    float A = RATIO * __expf(-dec_f(g_kmax));
    for (int i = t; i < ES; i += 288)
        ksm[i] = (i < MM) ? fmaf(A, g_ksumU[(size_t)bh*MM + i], RE*128.f) : 0.f;
    __syncthreads();

    if (t < DH) {                       // csum (scaled)
        float s = 0.f;
        for (int m = 0; m < MM; ++m) s += g_ctxU[((size_t)bh*MM + m)*DH + t];
        g_csA[(size_t)bh*DH + t] = fmaf(A, s, (float)MM * RE * g_vsum[(size_t)bh*DH + t]);
    } else if (t < 96) {                // kss
        int l = t - 64;
        float s = 0.f;
        for (int i = l; i < MM; i += 32) s += ksm[i];
#pragma unroll
        for (int o = 16; o; o >>= 1) s += __shfl_xor_sync(0xffffffffu, s, o);
        if (l == 0) g_kss[bh] = s;
    } else {                            // Tn, Emx : 6 warps over 128 rows
        int w = (t - 96) >> 5, l = t & 31;
        const float* Eb = g_Eq + (size_t)bh*NT*ES;
        for (int n = w; n < NT; n += 6) {
            const float* er = Eb + n*ES;
            float s = 0.f, mx = 0.f;
            for (int m = l; m < MM; m += 32) {
                float e = er[m];
                s  = fmaf(e, ksm[m], s);
                mx = fmaxf(mx, e);
            }
#pragma unroll
            for (int o = 16; o; o >>= 1) {
                s  += __shfl_xor_sync(0xffffffffu, s, o);
                mx  = fmaxf(mx, __shfl_xor_sync(0xffffffffu, mx, o));
            }
            if (l == 0) { g_Tn[(size_t)bh*NT + n] = s; g_Emx[(size_t)bh*NT + n] = mx; }
        }
    }
}

// ---------------- k3b: O = Eq @ ctx + epilogue ----------------
#define CTX_ST 68
#define K3B_SMEM (MM*CTX_ST*4)

__global__ __launch_bounds__(256, 2)
void k3b_out()
{
    extern __shared__ float ctx[];          // [266][68]
    __shared__ float Tn_s[NT], Emx_s[NT], qd_s[NT], cs_s[DH], vs_s[DH];
    __shared__ float sA, skss;
    int bh = blockIdx.x, t = threadIdx.x;

    if (t == 0) { sA = RATIO * __expf(-dec_f(g_kmax)); skss = g_kss[bh]; }
    if (t < DH) { vs_s[t] = g_vsum[(size_t)bh*DH + t]; cs_s[t] = g_csA[(size_t)bh*DH + t]; }
    if (t < NT) {
        Tn_s[t]  = g_Tn[(size_t)bh*NT + t];
        Emx_s[t] = g_Emx[(size_t)bh*NT + t];
        qd_s[t]  = g_qdg[(size_t)bh*NT + t];
    }
    __syncthreads();
    float A = sA;
    const float* cg = g_ctxU + (size_t)bh*MM*DH;
    for (int i = t; i < MM*DH; i += 256) {
        int m = i >> 6, d = i & 63;
        ctx[m*CTX_ST + d] = fmaf(A, cg[i], RE*vs_s[d]);
    }
    __syncthreads();

    int ng = t >> 3, dg = t & 7;
    int n0 = ng*4, d0 = dg*8;
    const float* Eb = g_Eq + (size_t)bh*NT*ES;
    const float* e0p = Eb + (n0+0)*ES;
    const float* e1p = Eb + (n0+1)*ES;
    const float* e2p = Eb + (n0+2)*ES;
    const float* e3p = Eb + (n0+3)*ES;
    float acc[32];
#pragma unroll
    for (int j = 0; j < 32; ++j) acc[j] = 0.f;

    const float* cp = ctx + d0;
#pragma unroll 2
    for (int m = 0; m < MM; ++m) {
        float e0 = e0p[m], e1 = e1p[m], e2 = e2p[m], e3 = e3p[m];
        float4 c0 = *(const float4*)(cp);
        float4 c1 = *(const float4*)(cp + 4);
        cp += CTX_ST;
        acc[ 0]=fmaf(e0,c0.x,acc[ 0]); acc[ 1]=fmaf(e0,c0.y,acc[ 1]);
        acc[ 2]=fmaf(e0,c0.z,acc[ 2]); acc[ 3]=fmaf(e0,c0.w,acc[ 3]);
        acc[ 4]=fmaf(e0,c1.x,acc[ 4]); acc[ 5]=fmaf(e0,c1.y,acc[ 5]);
        acc[ 6]=fmaf(e0,c1.z,acc[ 6]); acc[ 7]=fmaf(e0,c1.w,acc[ 7]);
        acc[ 8]=fmaf(e1,c0.x,acc[ 8]); acc[ 9]=fmaf(e1,c0.y,acc[ 9]);
        acc[10]=fmaf(e1,c0.z,acc[10]); acc[11]=fmaf(e1,c0.w,acc[11]);
        acc[12]=fmaf(e1,c1.x,acc[12]); acc[13]=fmaf(e1,c1.y,acc[13]);
        acc[14]=fmaf(e1,c1.z,acc[14]); acc[15]=fmaf(e1,c1.w,acc[15]);
        acc[16]=fmaf(e2,c0.x,acc[16]); acc[17]=fmaf(e2,c0.y,acc[17]);
        acc[18]=fmaf(e2,c0.z,acc[18]); acc[19]=fmaf(e2,c0.w,acc[19]);
        acc[20]=fmaf(e2,c1.x,acc[20]); acc[21]=fmaf(e2,c1.y,acc[21]);
        acc[22]=fmaf(e2,c1.z,acc[22]); acc[23]=fmaf(e2,c1.w,acc[23]);
        acc[24]=fmaf(e3,c0.x,acc[24]); acc[25]=fmaf(e3,c0.y,acc[25]);
        acc[26]=fmaf(e3,c0.z,acc[26]); acc[27]=fmaf(e3,c0.w,acc[27]);
        acc[28]=fmaf(e3,c1.x,acc[28]); acc[29]=fmaf(e3,c1.y,acc[29]);
        acc[30]=fmaf(e3,c1.z,acc[30]); acc[31]=fmaf(e3,c1.w,acc[31]);
    }

    int b = bh >> 3, h = bh & 7;
    float kss = skss;
#pragma unroll
    for (int i = 0; i < 4; ++i) {
        int n = n0 + i;
        float rq  = RATIO * __expf(-qd_s[n]) / Emx_s[n];
        float inv = 1.0f / fmaf(rq, Tn_s[n], RE*kss);
        float* og = g_o + ((size_t)(b*NT + n))*IN + h*DH + d0;
        float4 o0, o1;
        o0.x = fmaf(rq, acc[i*8+0], RE*cs_s[d0+0])*inv;
        o0.y = fmaf(rq, acc[i*8+1], RE*cs_s[d0+1])*inv;
        o0.z = fmaf(rq, acc[i*8+2], RE*cs_s[d0+2])*inv;
        o0.w = fmaf(rq, acc[i*8+3], RE*cs_s[d0+3])*inv;
        o1.x = fmaf(rq, acc[i*8+4], RE*cs_s[d0+4])*inv;
        o1.y = fmaf(rq, acc[i*8+5], RE*cs_s[d0+5])*inv;
        o1.z = fmaf(rq, acc[i*8+6], RE*cs_s[d0+6])*inv;
        o1.w = fmaf(rq, acc[i*8+7], RE*cs_s[d0+7])*inv;
        *(float4*)(og)     = o0;
        *(float4*)(og + 4) = o1;
    }
}

// ---------------- K4a: t = tokens + o @ Wo + bo ----------------
#define K4A_SMEM (IN*TD*4)

__global__ __launch_bounds__(256, 1)
void k4a_proj(const float* __restrict__ x,
              const float* __restrict__ Wo, const float* __restrict__ bo)
{
    extern __shared__ float wsm[];
    int b = blockIdx.x, tid = threadIdx.x;
    for (int i = tid; i < IN*TD; i += 256) wsm[i] = Wo[i];
    __syncthreads();

    int jt = tid & 15, ng = tid >> 4;
    int j4 = jt*4;
    float4 b4 = *(const float4*)(bo + j4);
    for (int n = ng; n < NT; n += 16) {
        float4 a = b4;
        const float* orow = g_o + ((size_t)(b*NT + n))*IN;
        for (int i = 0; i < IN; i += 4) {
            float4 ov = *(const float4*)(orow + i);
            float4 w0 = *(float4*)&wsm[(i+0)*64 + j4];
            float4 w1 = *(float4*)&wsm[(i+1)*64 + j4];
            float4 w2 = *(float4*)&wsm[(i+2)*64 + j4];
            float4 w3 = *(float4*)&wsm[(i+3)*64 + j4];
            a.x = fmaf(ov.x, w0.x, a.x); a.y = fmaf(ov.x, w0.y, a.y);
            a.z = fmaf(ov.x, w0.z, a.z); a.w = fmaf(ov.x, w0.w, a.w);
            a.x = fmaf(ov.y, w1.x, a.x); a.y = fmaf(ov.y, w1.y, a.y);
            a.z = fmaf(ov.y, w1.z, a.z); a.w = fmaf(ov.y, w1.w, a.w);
            a.x = fmaf(ov.z, w2.x, a.x); a.y = fmaf(ov.z, w2.y, a.y);
            a.z = fmaf(ov.z, w2.z, a.z); a.w = fmaf(ov.z, w2.w, a.w);
            a.x = fmaf(ov.w, w3.x, a.x); a.y = fmaf(ov.w, w3.y, a.y);
            a.z = fmaf(ov.w, w3.z, a.z); a.w = fmaf(ov.w, w3.w, a.w);
        }
        const float* xr = x + (size_t)b*NT*TD + n*TD + j4;
        float4 x4 = *(const float4*)xr;
        *(float4*)(g_t + (size_t)b*NT*TD + n*TD + j4) =
            make_float4(a.x + x4.x, a.y + x4.y, a.z + x4.z, a.w + x4.w);
    }
}

// ---------------- K4b: LN2 + FF(GELU) + LN3 + pool + head ----------------
#define K4B_SMEM ((NT*65 + NT*FH + TD*FH + 64 + 16)*4)

__global__ __launch_bounds__(256, 1)
void k4b_ff_head(const float* __restrict__ x,
                 const float* __restrict__ g2, const float* __restrict__ b2,
                 const float* __restrict__ W1, const float* __restrict__ c1,
                 const float* __restrict__ W2, const float* __restrict__ c2,
                 const float* __restrict__ g3, const float* __restrict__ b3,
                 const float* __restrict__ Wf1, const float* __restrict__ bf1,
                 const float* __restrict__ Wf2, const float* __restrict__ bf2,
                 float* __restrict__ out)
{
    extern __shared__ float sm4[];
    float* h2  = sm4;
    float* gsm = h2 + NT*65;
    float* wsm = gsm + NT*FH;
    float* psm = wsm + TD*FH;
    float* red = psm + 64;

    int b = blockIdx.x, tid = threadIdx.x;

    if (tid < NT) {
        const float* tr = g_t + ((size_t)(b*NT + tid))*TD;
        float tv[64];
#pragma unroll
        for (int j = 0; j < 16; ++j) {
            float4 t4 = *(const float4*)(tr + 4*j);
            tv[4*j]=t4.x; tv[4*j+1]=t4.y; tv[4*j+2]=t4.z; tv[4*j+3]=t4.w;
        }
        float mu = 0.f;
#pragma unroll
        for (int d = 0; d < 64; d++) mu += tv[d];
        mu *= (1.f/64.f);
        float var = 0.f;
#pragma unroll
        for (int d = 0; d < 64; d++) { float t = tv[d]-mu; var += t*t; }
        var *= (1.f/64.f);
        float inv = rsqrtf(var + 1e-5f);
#pragma unroll
        for (int d = 0; d < 64; d++)
            h2[tid*65 + d] = (tv[d]-mu)*inv*g2[d] + b2[d];
    }
    for (int i = tid; i < TD*FH; i += 256) wsm[i] = W1[i];
    __syncthreads();

    {
        int pt = tid & 63, grp = tid >> 6;
        int p4 = pt*4;
        float4 c14 = *(const float4*)(c1 + p4);
        for (int n = grp; n < NT; n += 4) {
            float4 a = c14;
#pragma unroll
            for (int j = 0; j < TD; ++j) {
                float hv = h2[n*65 + j];
                float4 w = *(float4*)&wsm[j*FH + p4];
                a.x = fmaf(hv, w.x, a.x); a.y = fmaf(hv, w.y, a.y);
                a.z = fmaf(hv, w.z, a.z); a.w = fmaf(hv, w.w, a.w);
            }
            a.x = 0.5f*a.x*(1.f + erff(a.x*0.70710678f));
            a.y = 0.5f*a.y*(1.f + erff(a.y*0.70710678f));
            a.z = 0.5f*a.z*(1.f + erff(a.z*0.70710678f));
            a.w = 0.5f*a.w*(1.f + erff(a.w*0.70710678f));
            *(float4*)&gsm[n*FH + p4] = a;
        }
    }
    __syncthreads();
    for (int i = tid; i < FH*TD; i += 256) wsm[i] = W2[i];
    __syncthreads();

    {
        int jt = tid & 15, grp = tid >> 4;
        int j4 = jt*4;
        float4 c24 = *(const float4*)(c2 + j4);
        for (int n = grp; n < NT; n += 16) {
            float4 a = c24;
            for (int p = 0; p < FH; ++p) {
                float gv = gsm[n*FH + p];
                float4 w = *(float4*)&wsm[p*64 + j4];
                a.x = fmaf(gv, w.x, a.x); a.y = fmaf(gv, w.y, a.y);
                a.z = fmaf(gv, w.z, a.z); a.w = fmaf(gv, w.w, a.w);
            }
            float4 t4 = *(const float4*)(g_t + (size_t)b*NT*TD + n*TD + j4);
            float4 x4 = *(const float4*)(x   + (size_t)b*NT*TD + n*TD + j4);
            h2[n*65 + j4 + 0] = a.x + t4.x + x4.x;
            h2[n*65 + j4 + 1] = a.y + t4.y + x4.y;
            h2[n*65 + j4 + 2] = a.z + t4.z + x4.z;
            h2[n*65 + j4 + 3] = a.w + t4.w + x4.w;
        }
    }
    __syncthreads();

    if (tid < NT) {
        float* r = &h2[tid*65];
        float mu = 0.f;
#pragma unroll
        for (int d = 0; d < 64; d++) mu += r[d];
        mu *= (1.f/64.f);
        float var = 0.f;
#pragma unroll
        for (int d = 0; d < 64; d++) { float t = r[d]-mu; var += t*t; }
        var *= (1.f/64.f);
        float inv = rsqrtf(var + 1e-5f);
#pragma unroll
        for (int d = 0; d < 64; d++)
            r[d] = (r[d]-mu)*inv*g3[d] + b3[d];
    }
    __syncthreads();

    if (tid < TD) {
        float s = 0.f;
        for (int n = 0; n < NT; ++n) s += h2[n*65 + tid];
        psm[tid] = s * (1.f/128.f);
    }
    __syncthreads();

    float val = 0.f;
    if (tid < 128) {
        float s = bf1[tid];
        for (int d = 0; d < TD; ++d)
            s = fmaf(psm[d], Wf1[d*128 + tid], s);
        s = fmaxf(s, 0.f);
        val = s * Wf2[tid];
    }
#pragma unroll
    for (int o = 16; o; o >>= 1)
        val += __shfl_xor_sync(0xffffffffu, val, o);
    if ((tid & 31) == 0) red[tid >> 5] = val;
    __syncthreads();
    if (tid == 0)
        out[b] = red[0] + red[1] + red[2] + red[3] + bf2[0];
}

// ---------------- launch ----------------
extern "C" void kernel_launch(void* const* d_in, const int* in_sizes, int n_in,
                              void* d_out, int out_size) {
    const float* x    = (const float*)d_in[0];
    const float* g1   = (const float*)d_in[1];
    const float* b1   = (const float*)d_in[2];
    const float* Wq   = (const float*)d_in[3];
    const float* bq   = (const float*)d_in[4];
    const float* Wk   = (const float*)d_in[5];
    const float* bk   = (const float*)d_in[6];
    const float* Wv   = (const float*)d_in[7];
    const float* bv   = (const float*)d_in[8];
    const float* Wo   = (const float*)d_in[9];
    const float* bo   = (const float*)d_in[10];
    const float* proj = (const float*)d_in[11];
    const float* g2   = (const float*)d_in[12];
    const float* b2   = (const float*)d_in[13];
    const float* W1   = (const float*)d_in[14];
    const float* c1   = (const float*)d_in[15];
    const float* W2   = (const float*)d_in[16];
    const float* c2   = (const float*)d_in[17];
    const float* g3   = (const float*)d_in[18];
    const float* b3   = (const float*)d_in[19];
    const float* Wf1  = (const float*)d_in[20];
    const float* bf1  = (const float*)d_in[21];
    const float* Wf2  = (const float*)d_in[22];
    const float* bf2  = (const float*)d_in[23];
    float* out = (float*)d_out;

    cudaFuncSetAttribute(k3b_out,    cudaFuncAttributeMaxDynamicSharedMemorySize, K3B_SMEM);
    cudaFuncSetAttribute(k4a_proj,   cudaFuncAttributeMaxDynamicSharedMemorySize, K4A_SMEM);
    cudaFuncSetAttribute(k4b_ff_head,cudaFuncAttributeMaxDynamicSharedMemorySize, K4B_SMEM);

    k_init<<<1, 1>>>();
    k1_ln_qkv<<<BB, 512>>>(x, g1, b1, Wq, bq, Wk, bk, Wv, bv);
    k2a_feat<<<BB*HH, FT>>>(proj);
    k3a_feat<<<BB*HH, FT>>>(proj);
    k2b_ctx<<<dim3(BB*HH, 3), 256>>>();
    k3x_stats<<<BB*HH, 288>>>();
    k3b_out<<<BB*HH, 256, K3B_SMEM>>>();
    k4a_proj<<<BB, 256, K4A_SMEM>>>(x, Wo, bo);
    k4b_ff_head<<<BB, 256, K4B_SMEM>>>(x, g2, b2, W1, c1, W2, c2,
                                       g3, b3, Wf1, bf1, Wf2, bf2, out);
}

// round 7
// speedup vs baseline: 1.1876x; 1.1876x over previous
#include <cuda_runtime.h>
#include <math.h>

#define BB 256
#define NT 128
#define TD 64
#define HH 8
#define DH 64
#define IN 512
#define MM 266
#define ES 272
#define FH 256

#define DN    0.35355339059327373f
#define RATIO 0.0613139076f
#define RE    6.13139076e-6f

__device__ float g_q[BB*HH*NT*DH];
__device__ float g_k[BB*HH*NT*DH];
__device__ float g_v[BB*HH*NT*DH];
__device__ float g_Ek[BB*HH*NT*ES];
__device__ float g_Eq[BB*HH*NT*ES];
__device__ float g_ctxU[BB*HH*MM*DH];
__device__ float g_ksumU[BB*HH*MM];
__device__ float g_vsum[BB*HH*DH];
__device__ float g_qdg[BB*HH*NT];
__device__ float g_Tn[BB*HH*NT];
__device__ float g_Emx[BB*HH*NT];
__device__ float g_csA[BB*HH*DH];
__device__ float g_kss[BB*HH];
__device__ float g_o[BB*NT*IN];
__device__ float g_t[BB*NT*TD];
__device__ unsigned g_kmax;

__device__ __forceinline__ unsigned enc_f(float f) {
    unsigned u = __float_as_uint(f);
    return (u & 0x80000000u) ? ~u : (u | 0x80000000u);
}
__device__ __forceinline__ float dec_f(unsigned k) {
    return (k & 0x80000000u) ? __uint_as_float(k & 0x7fffffffu)
                             : __uint_as_float(~k);
}
__device__ __forceinline__ float to_tf32(float x) {
    unsigned r;
    asm("cvt.rna.tf32.f32 %0, %1;" : "=r"(r) : "f"(x));
    return __uint_as_float(r);
}
__device__ __forceinline__ void mma_tf32(float& c0, float& c1, float& c2, float& c3,
                                         unsigned a0, unsigned a1, unsigned a2, unsigned a3,
                                         unsigned b0, unsigned b1)
{
    asm volatile(
        "mma.sync.aligned.m16n8k8.row.col.f32.tf32.tf32.f32 "
        "{%0,%1,%2,%3}, {%4,%5,%6,%7}, {%8,%9}, {%0,%1,%2,%3};"
        : "+f"(c0), "+f"(c1), "+f"(c2), "+f"(c3)
        : "r"(a0), "r"(a1), "r"(a2), "r"(a3), "r"(b0), "r"(b1));
}

__global__ void k_init() { g_kmax = 0u; }

// ---------------- K1: LN1 + QKV projection ----------------
__global__ __launch_bounds__(512, 1)
void k1_ln_qkv(const float* __restrict__ x,
               const float* __restrict__ g1, const float* __restrict__ b1,
               const float* __restrict__ Wq, const float* __restrict__ bq,
               const float* __restrict__ Wk, const float* __restrict__ bk,
               const float* __restrict__ Wv, const float* __restrict__ bv)
{
    __shared__ float hsm[NT*65];
    int b = blockIdx.x, tid = threadIdx.x;
    const float* xb = x + (size_t)b*NT*TD;
    for (int i = tid; i < NT*TD; i += 512)
        hsm[(i >> 6)*65 + (i & 63)] = xb[i];
    __syncthreads();
    if (tid < NT) {
        float* r = &hsm[tid*65];
        float mu = 0.f;
#pragma unroll
        for (int d = 0; d < 64; d++) mu += r[d];
        mu *= (1.f/64.f);
        float var = 0.f;
#pragma unroll
        for (int d = 0; d < 64; d++) { float t = r[d]-mu; var += t*t; }
        var *= (1.f/64.f);
        float inv = rsqrtf(var + 1e-5f);
#pragma unroll
        for (int d = 0; d < 64; d++) r[d] = (r[d]-mu)*inv*g1[d] + b1[d];
    }
    __syncthreads();

    int jt = tid & 127, ng = tid >> 7;
    int j4 = jt*4;
    int head = j4 >> 6, doff = j4 & 63;

#define PROJ_PASS(W, bias, dst_arr)                                         \
    {                                                                       \
        float4 bb4 = *(const float4*)((bias) + j4);                         \
        for (int it = 0; it < 32; ++it) {                                   \
            int n = it*4 + ng;                                              \
            float4 a = bb4;                                                 \
            _Pragma("unroll")                                               \
            for (int d = 0; d < 64; ++d) {                                  \
                float hv = hsm[n*65 + d];                                   \
                float4 w = *(const float4*)((W) + d*IN + j4);               \
                a.x = fmaf(hv, w.x, a.x); a.y = fmaf(hv, w.y, a.y);         \
                a.z = fmaf(hv, w.z, a.z); a.w = fmaf(hv, w.w, a.w);         \
            }                                                               \
            int dst = ((b*HH + head)*NT + n)*DH + doff;                     \
            *(float4*)((dst_arr) + dst) = a;                                \
        }                                                                   \
    }
    PROJ_PASS(Wq, bq, g_q)
    PROJ_PASS(Wk, bk, g_k)
    PROJ_PASS(Wv, bv, g_v)
#undef PROJ_PASS
}

// ---------------- kfeat: mma.sync tf32 feature maps (Ek and Eq) ----------------
#define XS_ST 68
#define PS_ST 68
#define KF_SMEM ((ES*PS_ST + NT*XS_ST)*4)   /* 73984 + 34816 = 108800 B */

__global__ __launch_bounds__(256, 2)
void kfeat(const float* __restrict__ proj)
{
    extern __shared__ float dsm[];
    float* Ps = dsm;                 // [272][68] tf32
    float* Xs = Ps + ES*PS_ST;       // [128][68] tf32
    __shared__ float diag[NT];
    __shared__ unsigned s_smax;

    int bh = blockIdx.x, t = threadIdx.x;
    int wid = t >> 5, lane = t & 31;
    int g = lane >> 2, q = lane & 3;
    int r0 = wid*16;
    int rA = r0 + g, rB = r0 + g + 8;

    const float* kg = g_k + (size_t)bh*NT*DH;
    const float* qg = g_q + (size_t)bh*NT*DH;

    if (t == 0) s_smax = 0u;

    // Ps fill (tf32-converted, zero pad rows >= MM)
    for (int i = t; i < ES*DH; i += 256) {
        int m = i >> 6, d = i & 63;
        Ps[m*PS_ST + d] = (m < MM) ? to_tf32(proj[m*64 + d]) : 0.f;
    }
    // Xs <- keys (scaled, tf32)
    for (int i = t; i < NT*DH; i += 256) {
        int r = i >> 6, d = i & 63;
        Xs[r*XS_ST + d] = to_tf32(kg[i] * DN);
    }
    if (t < NT) {
        float s = 0.f;
#pragma unroll
        for (int d = 0; d < 64; d++) { float v = kg[t*64+d]*DN; s = fmaf(v,v,s); }
        diag[t] = 0.5f * s;
    }
    __syncthreads();

    // ===== phase 1: keys =====
    {
        unsigned a[8][4];
#pragma unroll
        for (int kc = 0; kc < 8; ++kc) {
            a[kc][0] = __float_as_uint(Xs[rA*XS_ST + kc*8 + q]);
            a[kc][1] = __float_as_uint(Xs[rB*XS_ST + kc*8 + q]);
            a[kc][2] = __float_as_uint(Xs[rA*XS_ST + kc*8 + q + 4]);
            a[kc][3] = __float_as_uint(Xs[rB*XS_ST + kc*8 + q + 4]);
        }
        float dgA = diag[rA], dgB = diag[rB];
        float* EA = g_Ek + ((size_t)bh*NT + rA)*ES;
        float* EB = g_Ek + ((size_t)bh*NT + rB)*ES;
        float dmax = -1e30f;

        for (int nc = 0; nc < 34; ++nc) {
            float c0=0.f, c1=0.f, c2=0.f, c3=0.f;
            const float* pb = Ps + (nc*8 + g)*PS_ST + q;
#pragma unroll
            for (int kc = 0; kc < 8; ++kc) {
                unsigned b0 = __float_as_uint(pb[kc*8]);
                unsigned b1 = __float_as_uint(pb[kc*8 + 4]);
                mma_tf32(c0, c1, c2, c3,
                         a[kc][0], a[kc][1], a[kc][2], a[kc][3], b0, b1);
            }
            int n0 = nc*8 + 2*q;
            bool v0 = (n0 < MM), v1 = (n0+1 < MM);
            if (v0) dmax = fmaxf(dmax, fmaxf(c0, c2));
            if (v1) dmax = fmaxf(dmax, fmaxf(c1, c3));
            float2 eA = make_float2(__expf(c0 - dgA), __expf(c1 - dgA));
            float2 eB = make_float2(__expf(c2 - dgB), __expf(c3 - dgB));
            *(float2*)(EA + n0) = eA;
            *(float2*)(EB + n0) = eB;
        }
#pragma unroll
        for (int o = 16; o; o >>= 1)
            dmax = fmaxf(dmax, __shfl_xor_sync(0xffffffffu, dmax, o));
        if (lane == 0) atomicMax(&s_smax, enc_f(dmax));
    }
    __syncthreads();
    if (t == 0) atomicMax(&g_kmax, s_smax);

    // Xs <- queries
    for (int i = t; i < NT*DH; i += 256) {
        int r = i >> 6, d = i & 63;
        Xs[r*XS_ST + d] = to_tf32(qg[i] * DN);
    }
    if (t < NT) {
        float s = 0.f;
#pragma unroll
        for (int d = 0; d < 64; d++) { float v = qg[t*64+d]*DN; s = fmaf(v,v,s); }
        g_qdg[(size_t)bh*NT + t] = 0.5f * s;
    }
    __syncthreads();

    // ===== phase 2: queries =====
    {
        unsigned a[8][4];
#pragma unroll
        for (int kc = 0; kc < 8; ++kc) {
            a[kc][0] = __float_as_uint(Xs[rA*XS_ST + kc*8 + q]);
            a[kc][1] = __float_as_uint(Xs[rB*XS_ST + kc*8 + q]);
            a[kc][2] = __float_as_uint(Xs[rA*XS_ST + kc*8 + q + 4]);
            a[kc][3] = __float_as_uint(Xs[rB*XS_ST + kc*8 + q + 4]);
        }
        float* EA = g_Eq + ((size_t)bh*NT + rA)*ES;
        float* EB = g_Eq + ((size_t)bh*NT + rB)*ES;
        float emxA = 0.f, emxB = 0.f;

        for (int nc = 0; nc < 34; ++nc) {
            float c0=0.f, c1=0.f, c2=0.f, c3=0.f;
            const float* pb = Ps + (nc*8 + g)*PS_ST + q;
#pragma unroll
            for (int kc = 0; kc < 8; ++kc) {
                unsigned b0 = __float_as_uint(pb[kc*8]);
                unsigned b1 = __float_as_uint(pb[kc*8 + 4]);
                mma_tf32(c0, c1, c2, c3,
                         a[kc][0], a[kc][1], a[kc][2], a[kc][3], b0, b1);
            }
            int n0 = nc*8 + 2*q;
            bool v0 = (n0 < MM), v1 = (n0+1 < MM);
            float e0 = __expf(c0), e1 = __expf(c1);
            float e2 = __expf(c2), e3 = __expf(c3);
            if (v0) { emxA = fmaxf(emxA, e0); emxB = fmaxf(emxB, e2); }
            if (v1) { emxA = fmaxf(emxA, e1); emxB = fmaxf(emxB, e3); }
            *(float2*)(EA + n0) = make_float2(e0, e1);
            *(float2*)(EB + n0) = make_float2(e2, e3);
        }
        emxA = fmaxf(emxA, __shfl_xor_sync(0xffffffffu, emxA, 1));
        emxA = fmaxf(emxA, __shfl_xor_sync(0xffffffffu, emxA, 2));
        emxB = fmaxf(emxB, __shfl_xor_sync(0xffffffffu, emxB, 1));
        emxB = fmaxf(emxB, __shfl_xor_sync(0xffffffffu, emxB, 2));
        if (q == 0) {
            g_Emx[(size_t)bh*NT + rA] = emxA;
            g_Emx[(size_t)bh*NT + rB] = emxB;
        }
    }
}

// ---------------- k2b: ctxU = Ek^T @ V, ksumU, vsum ----------------
__global__ __launch_bounds__(256, 2)
void k2b_ctx()
{
    __shared__ float vs[NT*DH];
    int bh = blockIdx.x, t = threadIdx.x;
    int m0 = blockIdx.y << 7;
    const float* vg = g_v + (size_t)bh*NT*DH;
    for (int i = t; i < NT*DH; i += 256) vs[i] = vg[i];
    __syncthreads();

    int mg = t >> 3, dg = t & 7;
    int mb = m0 + mg*4, d0 = dg*8;
    if (mb < ES) {
        const float* Eb = g_Ek + (size_t)bh*NT*ES + mb;
        float acc[32], ksm[4];
#pragma unroll
        for (int j = 0; j < 32; ++j) acc[j] = 0.f;
#pragma unroll
        for (int j = 0; j < 4; ++j) ksm[j] = 0.f;

#pragma unroll 2
        for (int nn = 0; nn < NT; ++nn) {
            const float* er = Eb + nn*ES;
            float e0 = er[0], e1 = er[1], e2 = er[2], e3 = er[3];
            float4 v0 = *(const float4*)(vs + nn*64 + d0);
            float4 v1 = *(const float4*)(vs + nn*64 + d0 + 4);
            ksm[0]+=e0; ksm[1]+=e1; ksm[2]+=e2; ksm[3]+=e3;
            acc[ 0]=fmaf(e0,v0.x,acc[ 0]); acc[ 1]=fmaf(e0,v0.y,acc[ 1]);
            acc[ 2]=fmaf(e0,v0.z,acc[ 2]); acc[ 3]=fmaf(e0,v0.w,acc[ 3]);
            acc[ 4]=fmaf(e0,v1.x,acc[ 4]); acc[ 5]=fmaf(e0,v1.y,acc[ 5]);
            acc[ 6]=fmaf(e0,v1.z,acc[ 6]); acc[ 7]=fmaf(e0,v1.w,acc[ 7]);
            acc[ 8]=fmaf(e1,v0.x,acc[ 8]); acc[ 9]=fmaf(e1,v0.y,acc[ 9]);
            acc[10]=fmaf(e1,v0.z,acc[10]); acc[11]=fmaf(e1,v0.w,acc[11]);
            acc[12]=fmaf(e1,v1.x,acc[12]); acc[13]=fmaf(e1,v1.y,acc[13]);
            acc[14]=fmaf(e1,v1.z,acc[14]); acc[15]=fmaf(e1,v1.w,acc[15]);
            acc[16]=fmaf(e2,v0.x,acc[16]); acc[17]=fmaf(e2,v0.y,acc[17]);
            acc[18]=fmaf(e2,v0.z,acc[18]); acc[19]=fmaf(e2,v0.w,acc[19]);
            acc[20]=fmaf(e2,v1.x,acc[20]); acc[21]=fmaf(e2,v1.y,acc[21]);
            acc[22]=fmaf(e2,v1.z,acc[22]); acc[23]=fmaf(e2,v1.w,acc[23]);
            acc[24]=fmaf(e3,v0.x,acc[24]); acc[25]=fmaf(e3,v0.y,acc[25]);
            acc[26]=fmaf(e3,v0.z,acc[26]); acc[27]=fmaf(e3,v0.w,acc[27]);
            acc[28]=fmaf(e3,v1.x,acc[28]); acc[29]=fmaf(e3,v1.y,acc[29]);
            acc[30]=fmaf(e3,v1.z,acc[30]); acc[31]=fmaf(e3,v1.w,acc[31]);
        }
#pragma unroll
        for (int i = 0; i < 4; ++i) {
            int m = mb + i;
            if (m < MM) {
                float* dst = g_ctxU + ((size_t)bh*MM + m)*DH + d0;
                *(float4*)(dst)   = make_float4(acc[i*8  ],acc[i*8+1],acc[i*8+2],acc[i*8+3]);
                *(float4*)(dst+4) = make_float4(acc[i*8+4],acc[i*8+5],acc[i*8+6],acc[i*8+7]);
                if (dg == 0) g_ksumU[(size_t)bh*MM + m] = ksm[i];
            }
        }
    }
    if (blockIdx.y == 0 && t < DH) {
        float s = 0.f;
        for (int nn = 0; nn < NT; ++nn) s += vs[nn*64 + t];
        g_vsum[(size_t)bh*DH + t] = s;
    }
}

// ---------------- k3x: per-bh stats ----------------
__global__ __launch_bounds__(288, 4)
void k3x_stats()
{
    __shared__ float ksm[ES];
    int bh = blockIdx.x, t = threadIdx.x;
    float A = RATIO * __expf(-dec_f(g_kmax));
    for (int i = t; i < ES; i += 288)
        ksm[i] = (i < MM) ? fmaf(A, g_ksumU[(size_t)bh*MM + i], RE*128.f) : 0.f;
    __syncthreads();

    if (t < DH) {
        float s = 0.f;
        for (int m = 0; m < MM; ++m) s += g_ctxU[((size_t)bh*MM + m)*DH + t];
        g_csA[(size_t)bh*DH + t] = fmaf(A, s, (float)MM * RE * g_vsum[(size_t)bh*DH + t]);
    } else if (t < 96) {
        int l = t - 64;
        float s = 0.f;
        for (int i = l; i < MM; i += 32) s += ksm[i];
#pragma unroll
        for (int o = 16; o; o >>= 1) s += __shfl_xor_sync(0xffffffffu, s, o);
        if (l == 0) g_kss[bh] = s;
    } else {
        int w = (t - 96) >> 5, l = t & 31;
        const float* Eb = g_Eq + (size_t)bh*NT*ES;
        for (int nn = w; nn < NT; nn += 6) {
            const float* er = Eb + nn*ES;
            float s = 0.f;
            for (int m = l; m < MM; m += 32) s = fmaf(er[m], ksm[m], s);
#pragma unroll
            for (int o = 16; o; o >>= 1) s += __shfl_xor_sync(0xffffffffu, s, o);
            if (l == 0) g_Tn[(size_t)bh*NT + nn] = s;
        }
    }
}

// ---------------- k3b: O = Eq @ ctx + epilogue ----------------
#define CTX_ST 68
#define K3B_SMEM (MM*CTX_ST*4)

__global__ __launch_bounds__(256, 2)
void k3b_out()
{
    extern __shared__ float ctx[];
    __shared__ float Tn_s[NT], Emx_s[NT], qd_s[NT], cs_s[DH], vs_s[DH];
    __shared__ float sA, skss;
    int bh = blockIdx.x, t = threadIdx.x;

    if (t == 0) { sA = RATIO * __expf(-dec_f(g_kmax)); skss = g_kss[bh]; }
    if (t < DH) { vs_s[t] = g_vsum[(size_t)bh*DH + t]; cs_s[t] = g_csA[(size_t)bh*DH + t]; }
    if (t < NT) {
        Tn_s[t]  = g_Tn[(size_t)bh*NT + t];
        Emx_s[t] = g_Emx[(size_t)bh*NT + t];
        qd_s[t]  = g_qdg[(size_t)bh*NT + t];
    }
    __syncthreads();
    float A = sA;
    const float* cg = g_ctxU + (size_t)bh*MM*DH;
    for (int i = t; i < MM*DH; i += 256) {
        int m = i >> 6, d = i & 63;
        ctx[m*CTX_ST + d] = fmaf(A, cg[i], RE*vs_s[d]);
    }
    __syncthreads();

    int ng = t >> 3, dg = t & 7;
    int n0 = ng*4, d0 = dg*8;
    const float* Eb = g_Eq + (size_t)bh*NT*ES;
    const float* e0p = Eb + (n0+0)*ES;
    const float* e1p = Eb + (n0+1)*ES;
    const float* e2p = Eb + (n0+2)*ES;
    const float* e3p = Eb + (n0+3)*ES;
    float acc[32];
#pragma unroll
    for (int j = 0; j < 32; ++j) acc[j] = 0.f;

    const float* cp = ctx + d0;
#pragma unroll 2
    for (int m = 0; m < MM; ++m) {
        float e0 = e0p[m], e1 = e1p[m], e2 = e2p[m], e3 = e3p[m];
        float4 c0 = *(const float4*)(cp);
        float4 c1 = *(const float4*)(cp + 4);
        cp += CTX_ST;
        acc[ 0]=fmaf(e0,c0.x,acc[ 0]); acc[ 1]=fmaf(e0,c0.y,acc[ 1]);
        acc[ 2]=fmaf(e0,c0.z,acc[ 2]); acc[ 3]=fmaf(e0,c0.w,acc[ 3]);
        acc[ 4]=fmaf(e0,c1.x,acc[ 4]); acc[ 5]=fmaf(e0,c1.y,acc[ 5]);
        acc[ 6]=fmaf(e0,c1.z,acc[ 6]); acc[ 7]=fmaf(e0,c1.w,acc[ 7]);
        acc[ 8]=fmaf(e1,c0.x,acc[ 8]); acc[ 9]=fmaf(e1,c0.y,acc[ 9]);
        acc[10]=fmaf(e1,c0.z,acc[10]); acc[11]=fmaf(e1,c0.w,acc[11]);
        acc[12]=fmaf(e1,c1.x,acc[12]); acc[13]=fmaf(e1,c1.y,acc[13]);
        acc[14]=fmaf(e1,c1.z,acc[14]); acc[15]=fmaf(e1,c1.w,acc[15]);
        acc[16]=fmaf(e2,c0.x,acc[16]); acc[17]=fmaf(e2,c0.y,acc[17]);
        acc[18]=fmaf(e2,c0.z,acc[18]); acc[19]=fmaf(e2,c0.w,acc[19]);
        acc[20]=fmaf(e2,c1.x,acc[20]); acc[21]=fmaf(e2,c1.y,acc[21]);
        acc[22]=fmaf(e2,c1.z,acc[22]); acc[23]=fmaf(e2,c1.w,acc[23]);
        acc[24]=fmaf(e3,c0.x,acc[24]); acc[25]=fmaf(e3,c0.y,acc[25]);
        acc[26]=fmaf(e3,c0.z,acc[26]); acc[27]=fmaf(e3,c0.w,acc[27]);
        acc[28]=fmaf(e3,c1.x,acc[28]); acc[29]=fmaf(e3,c1.y,acc[29]);
        acc[30]=fmaf(e3,c1.z,acc[30]); acc[31]=fmaf(e3,c1.w,acc[31]);
    }

    int b = bh >> 3, h = bh & 7;
    float kss = skss;
#pragma unroll
    for (int i = 0; i < 4; ++i) {
        int nn = n0 + i;
        float rq  = RATIO * __expf(-qd_s[nn]) / Emx_s[nn];
        float inv = 1.0f / fmaf(rq, Tn_s[nn], RE*kss);
        float* og = g_o + ((size_t)(b*NT + nn))*IN + h*DH + d0;
        float4 o0, o1;
        o0.x = fmaf(rq, acc[i*8+0], RE*cs_s[d0+0])*inv;
        o0.y = fmaf(rq, acc[i*8+1], RE*cs_s[d0+1])*inv;
        o0.z = fmaf(rq, acc[i*8+2], RE*cs_s[d0+2])*inv;
        o0.w = fmaf(rq, acc[i*8+3], RE*cs_s[d0+3])*inv;
        o1.x = fmaf(rq, acc[i*8+4], RE*cs_s[d0+4])*inv;
        o1.y = fmaf(rq, acc[i*8+5], RE*cs_s[d0+5])*inv;
        o1.z = fmaf(rq, acc[i*8+6], RE*cs_s[d0+6])*inv;
        o1.w = fmaf(rq, acc[i*8+7], RE*cs_s[d0+7])*inv;
        *(float4*)(og)     = o0;
        *(float4*)(og + 4) = o1;
    }
}

// ---------------- K4a ----------------
#define K4A_SMEM (IN*TD*4)

__global__ __launch_bounds__(256, 1)
void k4a_proj(const float* __restrict__ x,
              const float* __restrict__ Wo, const float* __restrict__ bo)
{
    extern __shared__ float wsm[];
    int b = blockIdx.x, tid = threadIdx.x;
    for (int i = tid; i < IN*TD; i += 256) wsm[i] = Wo[i];
    __syncthreads();

    int jt = tid & 15, ng = tid >> 4;
    int j4 = jt*4;
    float4 b4 = *(const float4*)(bo + j4);
    for (int nn = ng; nn < NT; nn += 16) {
        float4 a = b4;
        const float* orow = g_o + ((size_t)(b*NT + nn))*IN;
        for (int i = 0; i < IN; i += 4) {
            float4 ov = *(const float4*)(orow + i);
            float4 w0 = *(float4*)&wsm[(i+0)*64 + j4];
            float4 w1 = *(float4*)&wsm[(i+1)*64 + j4];
            float4 w2 = *(float4*)&wsm[(i+2)*64 + j4];
            float4 w3 = *(float4*)&wsm[(i+3)*64 + j4];
            a.x = fmaf(ov.x, w0.x, a.x); a.y = fmaf(ov.x, w0.y, a.y);
            a.z = fmaf(ov.x, w0.z, a.z); a.w = fmaf(ov.x, w0.w, a.w);
            a.x = fmaf(ov.y, w1.x, a.x); a.y = fmaf(ov.y, w1.y, a.y);
            a.z = fmaf(ov.y, w1.z, a.z); a.w = fmaf(ov.y, w1.w, a.w);
            a.x = fmaf(ov.z, w2.x, a.x); a.y = fmaf(ov.z, w2.y, a.y);
            a.z = fmaf(ov.z, w2.z, a.z); a.w = fmaf(ov.z, w2.w, a.w);
            a.x = fmaf(ov.w, w3.x, a.x); a.y = fmaf(ov.w, w3.y, a.y);
            a.z = fmaf(ov.w, w3.z, a.z); a.w = fmaf(ov.w, w3.w, a.w);
        }
        const float* xr = x + (size_t)b*NT*TD + nn*TD + j4;
        float4 x4 = *(const float4*)xr;
        *(float4*)(g_t + (size_t)b*NT*TD + nn*TD + j4) =
            make_float4(a.x + x4.x, a.y + x4.y, a.z + x4.z, a.w + x4.w);
    }
}

// ---------------- K4b ----------------
#define K4B_SMEM ((NT*65 + NT*FH + TD*FH + 64 + 16)*4)

__global__ __launch_bounds__(256, 1)
void k4b_ff_head(const float* __restrict__ x,
                 const float* __restrict__ g2, const float* __restrict__ b2,
                 const float* __restrict__ W1, const float* __restrict__ c1,
                 const float* __restrict__ W2, const float* __restrict__ c2,
                 const float* __restrict__ g3, const float* __restrict__ b3,
                 const float* __restrict__ Wf1, const float* __restrict__ bf1,
                 const float* __restrict__ Wf2, const float* __restrict__ bf2,
                 float* __restrict__ out)
{
    extern __shared__ float sm4[];
    float* h2  = sm4;
    float* gsm = h2 + NT*65;
    float* wsm = gsm + NT*FH;
    float* psm = wsm + TD*FH;
    float* red = psm + 64;

    int b = blockIdx.x, tid = threadIdx.x;

    if (tid < NT) {
        const float* tr = g_t + ((size_t)(b*NT + tid))*TD;
        float tv[64];
#pragma unroll
        for (int j = 0; j < 16; ++j) {
            float4 t4 = *(const float4*)(tr + 4*j);
            tv[4*j]=t4.x; tv[4*j+1]=t4.y; tv[4*j+2]=t4.z; tv[4*j+3]=t4.w;
        }
        float mu = 0.f;
#pragma unroll
        for (int d = 0; d < 64; d++) mu += tv[d];
        mu *= (1.f/64.f);
        float var = 0.f;
#pragma unroll
        for (int d = 0; d < 64; d++) { float t = tv[d]-mu; var += t*t; }
        var *= (1.f/64.f);
        float inv = rsqrtf(var + 1e-5f);
#pragma unroll
        for (int d = 0; d < 64; d++)
            h2[tid*65 + d] = (tv[d]-mu)*inv*g2[d] + b2[d];
    }
    for (int i = tid; i < TD*FH; i += 256) wsm[i] = W1[i];
    __syncthreads();

    {
        int pt = tid & 63, grp = tid >> 6;
        int p4 = pt*4;
        float4 c14 = *(const float4*)(c1 + p4);
        for (int nn = grp; nn < NT; nn += 4) {
            float4 a = c14;
#pragma unroll
            for (int j = 0; j < TD; ++j) {
                float hv = h2[nn*65 + j];
                float4 w = *(float4*)&wsm[j*FH + p4];
                a.x = fmaf(hv, w.x, a.x); a.y = fmaf(hv, w.y, a.y);
                a.z = fmaf(hv, w.z, a.z); a.w = fmaf(hv, w.w, a.w);
            }
            a.x = 0.5f*a.x*(1.f + erff(a.x*0.70710678f));
            a.y = 0.5f*a.y*(1.f + erff(a.y*0.70710678f));
            a.z = 0.5f*a.z*(1.f + erff(a.z*0.70710678f));
            a.w = 0.5f*a.w*(1.f + erff(a.w*0.70710678f));
            *(float4*)&gsm[nn*FH + p4] = a;
        }
    }
    __syncthreads();
    for (int i = tid; i < FH*TD; i += 256) wsm[i] = W2[i];
    __syncthreads();

    {
        int jt = tid & 15, grp = tid >> 4;
        int j4 = jt*4;
        float4 c24 = *(const float4*)(c2 + j4);
        for (int nn = grp; nn < NT; nn += 16) {
            float4 a = c24;
            for (int p = 0; p < FH; ++p) {
                float gv = gsm[nn*FH + p];
                float4 w = *(float4*)&wsm[p*64 + j4];
                a.x = fmaf(gv, w.x, a.x); a.y = fmaf(gv, w.y, a.y);
                a.z = fmaf(gv, w.z, a.z); a.w = fmaf(gv, w.w, a.w);
            }
            float4 t4 = *(const float4*)(g_t + (size_t)b*NT*TD + nn*TD + j4);
            float4 x4 = *(const float4*)(x   + (size_t)b*NT*TD + nn*TD + j4);
            h2[nn*65 + j4 + 0] = a.x + t4.x + x4.x;
            h2[nn*65 + j4 + 1] = a.y + t4.y + x4.y;
            h2[nn*65 + j4 + 2] = a.z + t4.z + x4.z;
            h2[nn*65 + j4 + 3] = a.w + t4.w + x4.w;
        }
    }
    __syncthreads();

    if (tid < NT) {
        float* r = &h2[tid*65];
        float mu = 0.f;
#pragma unroll
        for (int d = 0; d < 64; d++) mu += r[d];
        mu *= (1.f/64.f);
        float var = 0.f;
#pragma unroll
        for (int d = 0; d < 64; d++) { float t = r[d]-mu; var += t*t; }
        var *= (1.f/64.f);
        float inv = rsqrtf(var + 1e-5f);
#pragma unroll
        for (int d = 0; d < 64; d++)
            r[d] = (r[d]-mu)*inv*g3[d] + b3[d];
    }
    __syncthreads();

    if (tid < TD) {
        float s = 0.f;
        for (int nn = 0; nn < NT; ++nn) s += h2[nn*65 + tid];
        psm[tid] = s * (1.f/128.f);
    }
    __syncthreads();

    float val = 0.f;
    if (tid < 128) {
        float s = bf1[tid];
        for (int d = 0; d < TD; ++d)
            s = fmaf(psm[d], Wf1[d*128 + tid], s);
        s = fmaxf(s, 0.f);
        val = s * Wf2[tid];
    }
#pragma unroll
    for (int o = 16; o; o >>= 1)
        val += __shfl_xor_sync(0xffffffffu, val, o);
    if ((tid & 31) == 0) red[tid >> 5] = val;
    __syncthreads();
    if (tid == 0)
        out[b] = red[0] + red[1] + red[2] + red[3] + bf2[0];
}

// ---------------- launch ----------------
extern "C" void kernel_launch(void* const* d_in, const int* in_sizes, int n_in,
                              void* d_out, int out_size) {
    const float* x    = (const float*)d_in[0];
    const float* g1   = (const float*)d_in[1];
    const float* b1   = (const float*)d_in[2];
    const float* Wq   = (const float*)d_in[3];
    const float* bq   = (const float*)d_in[4];
    const float* Wk   = (const float*)d_in[5];
    const float* bk   = (const float*)d_in[6];
    const float* Wv   = (const float*)d_in[7];
    const float* bv   = (const float*)d_in[8];
    const float* Wo   = (const float*)d_in[9];
    const float* bo   = (const float*)d_in[10];
    const float* proj = (const float*)d_in[11];
    const float* g2   = (const float*)d_in[12];
    const float* b2   = (const float*)d_in[13];
    const float* W1   = (const float*)d_in[14];
    const float* c1   = (const float*)d_in[15];
    const float* W2   = (const float*)d_in[16];
    const float* c2   = (const float*)d_in[17];
    const float* g3   = (const float*)d_in[18];
    const float* b3   = (const float*)d_in[19];
    const float* Wf1  = (const float*)d_in[20];
    const float* bf1  = (const float*)d_in[21];
    const float* Wf2  = (const float*)d_in[22];
    const float* bf2  = (const float*)d_in[23];
    float* out = (float*)d_out;

    cudaFuncSetAttribute(kfeat,      cudaFuncAttributeMaxDynamicSharedMemorySize, KF_SMEM);
    cudaFuncSetAttribute(k3b_out,    cudaFuncAttributeMaxDynamicSharedMemorySize, K3B_SMEM);
    cudaFuncSetAttribute(k4a_proj,   cudaFuncAttributeMaxDynamicSharedMemorySize, K4A_SMEM);
    cudaFuncSetAttribute(k4b_ff_head,cudaFuncAttributeMaxDynamicSharedMemorySize, K4B_SMEM);

    k_init<<<1, 1>>>();
    k1_ln_qkv<<<BB, 512>>>(x, g1, b1, Wq, bq, Wk, bk, Wv, bv);
    kfeat<<<BB*HH, 256, KF_SMEM>>>(proj);
    k2b_ctx<<<dim3(BB*HH, 3), 256>>>();
    k3x_stats<<<BB*HH, 288>>>();
    k3b_out<<<BB*HH, 256, K3B_SMEM>>>();
    k4a_proj<<<BB, 256, K4A_SMEM>>>(x, Wo, bo);
    k4b_ff_head<<<BB, 256, K4B_SMEM>>>(x, g2, b2, W1, c1, W2, c2,
                                       g3, b3, Wf1, bf1, Wf2, bf2, out);
}

// round 8
// speedup vs baseline: 1.4246x; 1.1996x over previous
#include <cuda_runtime.h>
#include <math.h>

#define BB 256
#define NT 128
#define TD 64
#define HH 8
#define DH 64
#define IN 512
#define MM 266
#define ES 272
#define FH 256

#define DN    0.35355339059327373f
#define RATIO 0.0613139076f
#define RE    6.13139076e-6f

__device__ float g_q[BB*HH*NT*DH];
__device__ float g_k[BB*HH*NT*DH];
__device__ float g_v[BB*HH*NT*DH];
__device__ float g_Ek[BB*HH*NT*ES];
__device__ float g_Eq[BB*HH*NT*ES];
__device__ float g_ctxT[BB*HH*DH*ES];   // [bh][d][m], pads zeroed
__device__ float g_ksumU[BB*HH*MM];
__device__ float g_vsum[BB*HH*DH];
__device__ float g_qdg[BB*HH*NT];
__device__ float g_Tn[BB*HH*NT];
__device__ float g_Emx[BB*HH*NT];
__device__ float g_csA[BB*HH*DH];
__device__ float g_kss[BB*HH];
__device__ float g_o[BB*NT*IN];
__device__ float g_t[BB*NT*TD];
__device__ unsigned g_kmax;

__device__ __forceinline__ unsigned enc_f(float f) {
    unsigned u = __float_as_uint(f);
    return (u & 0x80000000u) ? ~u : (u | 0x80000000u);
}
__device__ __forceinline__ float dec_f(unsigned k) {
    return (k & 0x80000000u) ? __uint_as_float(k & 0x7fffffffu)
                             : __uint_as_float(~k);
}
__device__ __forceinline__ float to_tf32(float x) {
    unsigned r;
    asm("cvt.rna.tf32.f32 %0, %1;" : "=r"(r) : "f"(x));
    return __uint_as_float(r);
}
__device__ __forceinline__ void mma_tf32(float& c0, float& c1, float& c2, float& c3,
                                         unsigned a0, unsigned a1, unsigned a2, unsigned a3,
                                         unsigned b0, unsigned b1)
{
    asm volatile(
        "mma.sync.aligned.m16n8k8.row.col.f32.tf32.tf32.f32 "
        "{%0,%1,%2,%3}, {%4,%5,%6,%7}, {%8,%9}, {%0,%1,%2,%3};"
        : "+f"(c0), "+f"(c1), "+f"(c2), "+f"(c3)
        : "r"(a0), "r"(a1), "r"(a2), "r"(a3), "r"(b0), "r"(b1));
}

__global__ void k_init() { g_kmax = 0u; }

// ---------------- K1: LN1 + QKV projection ----------------
__global__ __launch_bounds__(512, 1)
void k1_ln_qkv(const float* __restrict__ x,
               const float* __restrict__ g1, const float* __restrict__ b1,
               const float* __restrict__ Wq, const float* __restrict__ bq,
               const float* __restrict__ Wk, const float* __restrict__ bk,
               const float* __restrict__ Wv, const float* __restrict__ bv)
{
    __shared__ float hsm[NT*65];
    int b = blockIdx.x, tid = threadIdx.x;
    const float* xb = x + (size_t)b*NT*TD;
    for (int i = tid; i < NT*TD; i += 512)
        hsm[(i >> 6)*65 + (i & 63)] = xb[i];
    __syncthreads();
    if (tid < NT) {
        float* r = &hsm[tid*65];
        float mu = 0.f;
#pragma unroll
        for (int d = 0; d < 64; d++) mu += r[d];
        mu *= (1.f/64.f);
        float var = 0.f;
#pragma unroll
        for (int d = 0; d < 64; d++) { float t = r[d]-mu; var += t*t; }
        var *= (1.f/64.f);
        float inv = rsqrtf(var + 1e-5f);
#pragma unroll
        for (int d = 0; d < 64; d++) r[d] = (r[d]-mu)*inv*g1[d] + b1[d];
    }
    __syncthreads();

    int jt = tid & 127, ng = tid >> 7;
    int j4 = jt*4;
    int head = j4 >> 6, doff = j4 & 63;

#define PROJ_PASS(W, bias, dst_arr)                                         \
    {                                                                       \
        float4 bb4 = *(const float4*)((bias) + j4);                         \
        for (int it = 0; it < 32; ++it) {                                   \
            int n = it*4 + ng;                                              \
            float4 a = bb4;                                                 \
            _Pragma("unroll")                                               \
            for (int d = 0; d < 64; ++d) {                                  \
                float hv = hsm[n*65 + d];                                   \
                float4 w = *(const float4*)((W) + d*IN + j4);               \
                a.x = fmaf(hv, w.x, a.x); a.y = fmaf(hv, w.y, a.y);         \
                a.z = fmaf(hv, w.z, a.z); a.w = fmaf(hv, w.w, a.w);         \
            }                                                               \
            int dst = ((b*HH + head)*NT + n)*DH + doff;                     \
            *(float4*)((dst_arr) + dst) = a;                                \
        }                                                                   \
    }
    PROJ_PASS(Wq, bq, g_q)
    PROJ_PASS(Wk, bk, g_k)
    PROJ_PASS(Wv, bv, g_v)
#undef PROJ_PASS
}

// ---------------- kfeat: mma.sync tf32 feature maps ----------------
#define XS_ST 68
#define PS_ST 68
#define KF_SMEM ((ES*PS_ST + NT*XS_ST)*4)

__global__ __launch_bounds__(256, 2)
void kfeat(const float* __restrict__ proj)
{
    extern __shared__ float dsm[];
    float* Ps = dsm;
    float* Xs = Ps + ES*PS_ST;
    __shared__ float diag[NT];
    __shared__ unsigned s_smax;

    int bh = blockIdx.x, t = threadIdx.x;
    int wid = t >> 5, lane = t & 31;
    int g = lane >> 2, q = lane & 3;
    int r0 = wid*16;
    int rA = r0 + g, rB = r0 + g + 8;

    const float* kg = g_k + (size_t)bh*NT*DH;
    const float* qg = g_q + (size_t)bh*NT*DH;

    if (t == 0) s_smax = 0u;

    for (int i = t; i < ES*DH; i += 256) {
        int m = i >> 6, d = i & 63;
        Ps[m*PS_ST + d] = (m < MM) ? to_tf32(proj[m*64 + d]) : 0.f;
    }
    for (int i = t; i < NT*DH; i += 256) {
        int r = i >> 6, d = i & 63;
        Xs[r*XS_ST + d] = to_tf32(kg[i] * DN);
    }
    if (t < NT) {
        float s = 0.f;
#pragma unroll
        for (int d = 0; d < 64; d++) { float v = kg[t*64+d]*DN; s = fmaf(v,v,s); }
        diag[t] = 0.5f * s;
    }
    __syncthreads();

    // keys
    {
        unsigned a[8][4];
#pragma unroll
        for (int kc = 0; kc < 8; ++kc) {
            a[kc][0] = __float_as_uint(Xs[rA*XS_ST + kc*8 + q]);
            a[kc][1] = __float_as_uint(Xs[rB*XS_ST + kc*8 + q]);
            a[kc][2] = __float_as_uint(Xs[rA*XS_ST + kc*8 + q + 4]);
            a[kc][3] = __float_as_uint(Xs[rB*XS_ST + kc*8 + q + 4]);
        }
        float dgA = diag[rA], dgB = diag[rB];
        float* EA = g_Ek + ((size_t)bh*NT + rA)*ES;
        float* EB = g_Ek + ((size_t)bh*NT + rB)*ES;
        float dmax = -1e30f;

        for (int nc = 0; nc < 34; ++nc) {
            float c0=0.f, c1=0.f, c2=0.f, c3=0.f;
            const float* pb = Ps + (nc*8 + g)*PS_ST + q;
#pragma unroll
            for (int kc = 0; kc < 8; ++kc) {
                unsigned b0 = __float_as_uint(pb[kc*8]);
                unsigned b1 = __float_as_uint(pb[kc*8 + 4]);
                mma_tf32(c0, c1, c2, c3,
                         a[kc][0], a[kc][1], a[kc][2], a[kc][3], b0, b1);
            }
            int n0 = nc*8 + 2*q;
            bool v0 = (n0 < MM), v1 = (n0+1 < MM);
            if (v0) dmax = fmaxf(dmax, fmaxf(c0, c2));
            if (v1) dmax = fmaxf(dmax, fmaxf(c1, c3));
            *(float2*)(EA + n0) = make_float2(__expf(c0 - dgA), __expf(c1 - dgA));
            *(float2*)(EB + n0) = make_float2(__expf(c2 - dgB), __expf(c3 - dgB));
        }
#pragma unroll
        for (int o = 16; o; o >>= 1)
            dmax = fmaxf(dmax, __shfl_xor_sync(0xffffffffu, dmax, o));
        if (lane == 0) atomicMax(&s_smax, enc_f(dmax));
    }
    __syncthreads();
    if (t == 0) atomicMax(&g_kmax, s_smax);

    for (int i = t; i < NT*DH; i += 256) {
        int r = i >> 6, d = i & 63;
        Xs[r*XS_ST + d] = to_tf32(qg[i] * DN);
    }
    if (t < NT) {
        float s = 0.f;
#pragma unroll
        for (int d = 0; d < 64; d++) { float v = qg[t*64+d]*DN; s = fmaf(v,v,s); }
        g_qdg[(size_t)bh*NT + t] = 0.5f * s;
    }
    __syncthreads();

    // queries
    {
        unsigned a[8][4];
#pragma unroll
        for (int kc = 0; kc < 8; ++kc) {
            a[kc][0] = __float_as_uint(Xs[rA*XS_ST + kc*8 + q]);
            a[kc][1] = __float_as_uint(Xs[rB*XS_ST + kc*8 + q]);
            a[kc][2] = __float_as_uint(Xs[rA*XS_ST + kc*8 + q + 4]);
            a[kc][3] = __float_as_uint(Xs[rB*XS_ST + kc*8 + q + 4]);
        }
        float* EA = g_Eq + ((size_t)bh*NT + rA)*ES;
        float* EB = g_Eq + ((size_t)bh*NT + rB)*ES;
        float emxA = 0.f, emxB = 0.f;

        for (int nc = 0; nc < 34; ++nc) {
            float c0=0.f, c1=0.f, c2=0.f, c3=0.f;
            const float* pb = Ps + (nc*8 + g)*PS_ST + q;
#pragma unroll
            for (int kc = 0; kc < 8; ++kc) {
                unsigned b0 = __float_as_uint(pb[kc*8]);
                unsigned b1 = __float_as_uint(pb[kc*8 + 4]);
                mma_tf32(c0, c1, c2, c3,
                         a[kc][0], a[kc][1], a[kc][2], a[kc][3], b0, b1);
            }
            int n0 = nc*8 + 2*q;
            bool v0 = (n0 < MM), v1 = (n0+1 < MM);
            float e0 = __expf(c0), e1 = __expf(c1);
            float e2 = __expf(c2), e3 = __expf(c3);
            if (v0) { emxA = fmaxf(emxA, e0); emxB = fmaxf(emxB, e2); }
            if (v1) { emxA = fmaxf(emxA, e1); emxB = fmaxf(emxB, e3); }
            *(float2*)(EA + n0) = make_float2(e0, e1);
            *(float2*)(EB + n0) = make_float2(e2, e3);
        }
        emxA = fmaxf(emxA, __shfl_xor_sync(0xffffffffu, emxA, 1));
        emxA = fmaxf(emxA, __shfl_xor_sync(0xffffffffu, emxA, 2));
        emxB = fmaxf(emxB, __shfl_xor_sync(0xffffffffu, emxB, 1));
        emxB = fmaxf(emxB, __shfl_xor_sync(0xffffffffu, emxB, 2));
        if (q == 0) {
            g_Emx[(size_t)bh*NT + rA] = emxA;
            g_Emx[(size_t)bh*NT + rB] = emxB;
        }
    }
}

// ---------------- k2b_mma: ctxT = V^T @ Ek (tf32 mma), ksum, vsum ----------------
#define EKT_ST 68
#define K2B_SMEM ((ES*EKT_ST + DH*EKT_ST)*4)   /* 91392 B */

__global__ __launch_bounds__(256, 2)
void k2b_mma()
{
    extern __shared__ float sm[];
    float* EkTs = sm;               // [272 m][64 n] stride 68
    float* Vts  = sm + ES*EKT_ST;   // [64 d][64 n] stride 68

    int bh = blockIdx.x, t = threadIdx.x;
    int wid = t >> 5, lane = t & 31;
    int g = lane >> 2, q = lane & 3;
    int mtile = wid >> 1;            // 0..3 → d rows
    int ntb = (wid & 1) * 17;        // 17 n-tiles (m cols)

    const float* Ekg = g_Ek + (size_t)bh*NT*ES;
    const float* vg  = g_v  + (size_t)bh*NT*DH;

    float acc[17][4];
#pragma unroll
    for (int j = 0; j < 17; ++j) { acc[j][0]=0.f; acc[j][1]=0.f; acc[j][2]=0.f; acc[j][3]=0.f; }
    float ks0 = 0.f, ks1 = 0.f, vs_r = 0.f;

    for (int c = 0; c < 2; ++c) {
        int n0 = c*64;
        for (int i = t; i < 64*64; i += 256) {
            int n = i >> 6, d = i & 63;
            Vts[d*EKT_ST + n] = vg[(n0+n)*64 + d];
        }
        for (int i = t; i < 64*ES; i += 256) {
            int n = i / ES, m = i - n*ES;
            EkTs[m*EKT_ST + n] = Ekg[(size_t)(n0+n)*ES + m];
        }
        __syncthreads();

        // ksum/vsum partials
        {
            float s = 0.f;
            const float4* r4 = (const float4*)(EkTs + t*EKT_ST);
#pragma unroll
            for (int j = 0; j < 16; ++j) { float4 v = r4[j]; s += (v.x+v.y)+(v.z+v.w); }
            ks0 += s;
            if (t < 16) {
                float s2 = 0.f;
                const float4* r2 = (const float4*)(EkTs + (t+256)*EKT_ST);
#pragma unroll
                for (int j = 0; j < 16; ++j) { float4 v = r2[j]; s2 += (v.x+v.y)+(v.z+v.w); }
                ks1 += s2;
            }
            if (t < 64) {
                float sv = 0.f;
                const float4* rv = (const float4*)(Vts + t*EKT_ST);
#pragma unroll
                for (int j = 0; j < 16; ++j) { float4 v = rv[j]; sv += (v.x+v.y)+(v.z+v.w); }
                vs_r += sv;
            }
        }

        // MMA
#pragma unroll
        for (int ks = 0; ks < 8; ++ks) {
            unsigned a0 = __float_as_uint(Vts[(mtile*16+g)*EKT_ST + ks*8 + q]);
            unsigned a1 = __float_as_uint(Vts[(mtile*16+g+8)*EKT_ST + ks*8 + q]);
            unsigned a2 = __float_as_uint(Vts[(mtile*16+g)*EKT_ST + ks*8 + q + 4]);
            unsigned a3 = __float_as_uint(Vts[(mtile*16+g+8)*EKT_ST + ks*8 + q + 4]);
#pragma unroll
            for (int j = 0; j < 17; ++j) {
                int mrow = (ntb + j)*8 + g;
                unsigned b0 = __float_as_uint(EkTs[mrow*EKT_ST + ks*8 + q]);
                unsigned b1 = __float_as_uint(EkTs[mrow*EKT_ST + ks*8 + q + 4]);
                mma_tf32(acc[j][0], acc[j][1], acc[j][2], acc[j][3],
                         a0, a1, a2, a3, b0, b1);
            }
        }
        __syncthreads();
    }

    // epilogue: write ctxT [d][m], pads zeroed
    int dA = mtile*16 + g, dB = dA + 8;
    float* ctA = g_ctxT + ((size_t)bh*DH + dA)*ES;
    float* ctB = g_ctxT + ((size_t)bh*DH + dB)*ES;
#pragma unroll
    for (int j = 0; j < 17; ++j) {
        int m0 = (ntb + j)*8 + 2*q;
        float e0 = (m0   < MM) ? acc[j][0] : 0.f;
        float e1 = (m0+1 < MM) ? acc[j][1] : 0.f;
        float e2 = (m0   < MM) ? acc[j][2] : 0.f;
        float e3 = (m0+1 < MM) ? acc[j][3] : 0.f;
        *(float2*)(ctA + m0) = make_float2(e0, e1);
        *(float2*)(ctB + m0) = make_float2(e2, e3);
    }
    if (t < MM) g_ksumU[(size_t)bh*MM + t] = ks0;
    if (t < 16 && t + 256 < MM) g_ksumU[(size_t)bh*MM + t + 256] = ks1;
    if (t < DH) g_vsum[(size_t)bh*DH + t] = vs_r;
}

// ---------------- k3x: per-bh stats (warp-coalesced) ----------------
__global__ __launch_bounds__(256, 4)
void k3x_stats()
{
    __shared__ float ksm[ES];
    int bh = blockIdx.x, t = threadIdx.x;
    int wid = t >> 5, lane = t & 31;
    float A = RATIO * __expf(-dec_f(g_kmax));
    for (int i = t; i < ES; i += 256)
        ksm[i] = (i < MM) ? fmaf(A, g_ksumU[(size_t)bh*MM + i], RE*128.f) : 0.f;
    __syncthreads();

    // csA: warp w handles d rows w*8..w*8+7
    for (int j = 0; j < 8; ++j) {
        int d = wid*8 + j;
        const float* row = g_ctxT + ((size_t)bh*DH + d)*ES;
        float s = 0.f;
        for (int m = lane; m < MM; m += 32) s += row[m];
#pragma unroll
        for (int o = 16; o; o >>= 1) s += __shfl_xor_sync(0xffffffffu, s, o);
        if (lane == 0)
            g_csA[(size_t)bh*DH + d] = fmaf(A, s, (float)MM * RE * g_vsum[(size_t)bh*DH + d]);
    }
    if (wid == 0) {
        float s = 0.f;
        for (int i = lane; i < MM; i += 32) s += ksm[i];
#pragma unroll
        for (int o = 16; o; o >>= 1) s += __shfl_xor_sync(0xffffffffu, s, o);
        if (lane == 0) g_kss[bh] = s;
    }
    // Tn: warp w handles n rows w*16..w*16+15
    const float* Eb = g_Eq + (size_t)bh*NT*ES;
    for (int j = 0; j < 16; ++j) {
        int n = wid*16 + j;
        const float* er = Eb + (size_t)n*ES;
        float s = 0.f;
        for (int m = lane; m < MM; m += 32) s = fmaf(er[m], ksm[m], s);
#pragma unroll
        for (int o = 16; o; o >>= 1) s += __shfl_xor_sync(0xffffffffu, s, o);
        if (lane == 0) g_Tn[(size_t)bh*NT + n] = s;
    }
}

// ---------------- k3b_mma: O = Eq @ ctx_scaled (tf32 mma) + epilogue ----------------
#define EQ_ST 137
#define K3B_SMEM ((NT*EQ_ST + DH*EQ_ST)*4)   /* 105216 B */

__global__ __launch_bounds__(512, 1)
void k3b_mma()
{
    extern __shared__ float sm[];
    float* Eqs   = sm;              // [128][136] stride 137
    float* ctxTs = sm + NT*EQ_ST;   // [64][136] stride 137
    __shared__ float qd_s[NT], Emx_s[NT], Tn_s[NT], cs_s[DH], vs_s[DH];
    __shared__ float sA, skss;

    int bh = blockIdx.x, t = threadIdx.x;
    int wid = t >> 5, lane = t & 31;
    int g = lane >> 2, q = lane & 3;
    int mtile = wid >> 1;          // n rows
    int dbase = (wid & 1)*32;      // d cols

    if (t == 0) { sA = RATIO * __expf(-dec_f(g_kmax)); skss = g_kss[bh]; }
    if (t < NT) {
        qd_s[t]  = g_qdg[(size_t)bh*NT + t];
        Emx_s[t] = g_Emx[(size_t)bh*NT + t];
        Tn_s[t]  = g_Tn[(size_t)bh*NT + t];
    }
    if (t < DH) {
        cs_s[t] = g_csA[(size_t)bh*DH + t];
        vs_s[t] = g_vsum[(size_t)bh*DH + t];
    }
    __syncthreads();
    float A = sA;

    const float* Eqg = g_Eq + (size_t)bh*NT*ES;
    const float* ctg = g_ctxT + (size_t)bh*DH*ES;

    float acc[4][4];
#pragma unroll
    for (int j = 0; j < 4; ++j) { acc[j][0]=0.f; acc[j][1]=0.f; acc[j][2]=0.f; acc[j][3]=0.f; }

    for (int c = 0; c < 2; ++c) {
        int m0 = c*136;
        for (int i = t; i < NT*136; i += 512) {
            int r = i / 136, cc = i - r*136;
            Eqs[r*EQ_ST + cc] = Eqg[(size_t)r*ES + m0 + cc];
        }
        for (int i = t; i < DH*136; i += 512) {
            int d = i / 136, cc = i - d*136;
            int mg = m0 + cc;
            float raw = ctg[(size_t)d*ES + mg];
            ctxTs[d*EQ_ST + cc] = (mg < MM) ? fmaf(A, raw, RE*vs_s[d]) : 0.f;
        }
        __syncthreads();

#pragma unroll
        for (int ks = 0; ks < 17; ++ks) {
            unsigned a0 = __float_as_uint(Eqs[(mtile*16+g)*EQ_ST + ks*8 + q]);
            unsigned a1 = __float_as_uint(Eqs[(mtile*16+g+8)*EQ_ST + ks*8 + q]);
            unsigned a2 = __float_as_uint(Eqs[(mtile*16+g)*EQ_ST + ks*8 + q + 4]);
            unsigned a3 = __float_as_uint(Eqs[(mtile*16+g+8)*EQ_ST + ks*8 + q + 4]);
#pragma unroll
            for (int nt = 0; nt < 4; ++nt) {
                int drow = dbase + nt*8 + g;
                unsigned b0 = __float_as_uint(ctxTs[drow*EQ_ST + ks*8 + q]);
                unsigned b1 = __float_as_uint(ctxTs[drow*EQ_ST + ks*8 + q + 4]);
                mma_tf32(acc[nt][0], acc[nt][1], acc[nt][2], acc[nt][3],
                         a0, a1, a2, a3, b0, b1);
            }
        }
        __syncthreads();
    }

    // epilogue
    int rA = mtile*16 + g, rB = rA + 8;
    float rqA = RATIO * __expf(-qd_s[rA]) / Emx_s[rA];
    float rqB = RATIO * __expf(-qd_s[rB]) / Emx_s[rB];
    float kss = skss;
    float invA = 1.0f / fmaf(rqA, Tn_s[rA], RE*kss);
    float invB = 1.0f / fmaf(rqB, Tn_s[rB], RE*kss);
    int b = bh >> 3, h = bh & 7;
    float* oA = g_o + ((size_t)(b*NT + rA))*IN + h*DH;
    float* oB = g_o + ((size_t)(b*NT + rB))*IN + h*DH;
#pragma unroll
    for (int nt = 0; nt < 4; ++nt) {
        int d = dbase + nt*8 + 2*q;
        float2 vA, vB;
        vA.x = fmaf(rqA, acc[nt][0], RE*cs_s[d  ])*invA;
        vA.y = fmaf(rqA, acc[nt][1], RE*cs_s[d+1])*invA;
        vB.x = fmaf(rqB, acc[nt][2], RE*cs_s[d  ])*invB;
        vB.y = fmaf(rqB, acc[nt][3], RE*cs_s[d+1])*invB;
        *(float2*)(oA + d) = vA;
        *(float2*)(oB + d) = vB;
    }
}

// ---------------- K4a ----------------
#define K4A_SMEM (IN*TD*4)

__global__ __launch_bounds__(256, 1)
void k4a_proj(const float* __restrict__ x,
              const float* __restrict__ Wo, const float* __restrict__ bo)
{
    extern __shared__ float wsm[];
    int b = blockIdx.x, tid = threadIdx.x;
    for (int i = tid; i < IN*TD; i += 256) wsm[i] = Wo[i];
    __syncthreads();

    int jt = tid & 15, ng = tid >> 4;
    int j4 = jt*4;
    float4 b4 = *(const float4*)(bo + j4);
    for (int nn = ng; nn < NT; nn += 16) {
        float4 a = b4;
        const float* orow = g_o + ((size_t)(b*NT + nn))*IN;
        for (int i = 0; i < IN; i += 4) {
            float4 ov = *(const float4*)(orow + i);
            float4 w0 = *(float4*)&wsm[(i+0)*64 + j4];
            float4 w1 = *(float4*)&wsm[(i+1)*64 + j4];
            float4 w2 = *(float4*)&wsm[(i+2)*64 + j4];
            float4 w3 = *(float4*)&wsm[(i+3)*64 + j4];
            a.x = fmaf(ov.x, w0.x, a.x); a.y = fmaf(ov.x, w0.y, a.y);
            a.z = fmaf(ov.x, w0.z, a.z); a.w = fmaf(ov.x, w0.w, a.w);
            a.x = fmaf(ov.y, w1.x, a.x); a.y = fmaf(ov.y, w1.y, a.y);
            a.z = fmaf(ov.y, w1.z, a.z); a.w = fmaf(ov.y, w1.w, a.w);
            a.x = fmaf(ov.z, w2.x, a.x); a.y = fmaf(ov.z, w2.y, a.y);
            a.z = fmaf(ov.z, w2.z, a.z); a.w = fmaf(ov.z, w2.w, a.w);
            a.x = fmaf(ov.w, w3.x, a.x); a.y = fmaf(ov.w, w3.y, a.y);
            a.z = fmaf(ov.w, w3.z, a.z); a.w = fmaf(ov.w, w3.w, a.w);
        }
        const float* xr = x + (size_t)b*NT*TD + nn*TD + j4;
        float4 x4 = *(const float4*)xr;
        *(float4*)(g_t + (size_t)b*NT*TD + nn*TD + j4) =
            make_float4(a.x + x4.x, a.y + x4.y, a.z + x4.z, a.w + x4.w);
    }
}

// ---------------- K4b ----------------
#define K4B_SMEM ((NT*65 + NT*FH + TD*FH + 64 + 16)*4)

__global__ __launch_bounds__(256, 1)
void k4b_ff_head(const float* __restrict__ x,
                 const float* __restrict__ g2, const float* __restrict__ b2,
                 const float* __restrict__ W1, const float* __restrict__ c1,
                 const float* __restrict__ W2, const float* __restrict__ c2,
                 const float* __restrict__ g3, const float* __restrict__ b3,
                 const float* __restrict__ Wf1, const float* __restrict__ bf1,
                 const float* __restrict__ Wf2, const float* __restrict__ bf2,
                 float* __restrict__ out)
{
    extern __shared__ float sm4[];
    float* h2  = sm4;
    float* gsm = h2 + NT*65;
    float* wsm = gsm + NT*FH;
    float* psm = wsm + TD*FH;
    float* red = psm + 64;

    int b = blockIdx.x, tid = threadIdx.x;

    if (tid < NT) {
        const float* tr = g_t + ((size_t)(b*NT + tid))*TD;
        float tv[64];
#pragma unroll
        for (int j = 0; j < 16; ++j) {
            float4 t4 = *(const float4*)(tr + 4*j);
            tv[4*j]=t4.x; tv[4*j+1]=t4.y; tv[4*j+2]=t4.z; tv[4*j+3]=t4.w;
        }
        float mu = 0.f;
#pragma unroll
        for (int d = 0; d < 64; d++) mu += tv[d];
        mu *= (1.f/64.f);
        float var = 0.f;
#pragma unroll
        for (int d = 0; d < 64; d++) { float t = tv[d]-mu; var += t*t; }
        var *= (1.f/64.f);
        float inv = rsqrtf(var + 1e-5f);
#pragma unroll
        for (int d = 0; d < 64; d++)
            h2[tid*65 + d] = (tv[d]-mu)*inv*g2[d] + b2[d];
    }
    for (int i = tid; i < TD*FH; i += 256) wsm[i] = W1[i];
    __syncthreads();

    {
        int pt = tid & 63, grp = tid >> 6;
        int p4 = pt*4;
        float4 c14 = *(const float4*)(c1 + p4);
        for (int nn = grp; nn < NT; nn += 4) {
            float4 a = c14;
#pragma unroll
            for (int j = 0; j < TD; ++j) {
                float hv = h2[nn*65 + j];
                float4 w = *(float4*)&wsm[j*FH + p4];
                a.x = fmaf(hv, w.x, a.x); a.y = fmaf(hv, w.y, a.y);
                a.z = fmaf(hv, w.z, a.z); a.w = fmaf(hv, w.w, a.w);
            }
            a.x = 0.5f*a.x*(1.f + erff(a.x*0.70710678f));
            a.y = 0.5f*a.y*(1.f + erff(a.y*0.70710678f));
            a.z = 0.5f*a.z*(1.f + erff(a.z*0.70710678f));
            a.w = 0.5f*a.w*(1.f + erff(a.w*0.70710678f));
            *(float4*)&gsm[nn*FH + p4] = a;
        }
    }
    __syncthreads();
    for (int i = tid; i < FH*TD; i += 256) wsm[i] = W2[i];
    __syncthreads();

    {
        int jt = tid & 15, grp = tid >> 4;
        int j4 = jt*4;
        float4 c24 = *(const float4*)(c2 + j4);
        for (int nn = grp; nn < NT; nn += 16) {
            float4 a = c24;
            for (int p = 0; p < FH; ++p) {
                float gv = gsm[nn*FH + p];
                float4 w = *(float4*)&wsm[p*64 + j4];
                a.x = fmaf(gv, w.x, a.x); a.y = fmaf(gv, w.y, a.y);
                a.z = fmaf(gv, w.z, a.z); a.w = fmaf(gv, w.w, a.w);
            }
            float4 t4 = *(const float4*)(g_t + (size_t)b*NT*TD + nn*TD + j4);
            float4 x4 = *(const float4*)(x   + (size_t)b*NT*TD + nn*TD + j4);
            h2[nn*65 + j4 + 0] = a.x + t4.x + x4.x;
            h2[nn*65 + j4 + 1] = a.y + t4.y + x4.y;
            h2[nn*65 + j4 + 2] = a.z + t4.z + x4.z;
            h2[nn*65 + j4 + 3] = a.w + t4.w + x4.w;
        }
    }
    __syncthreads();

    if (tid < NT) {
        float* r = &h2[tid*65];
        float mu = 0.f;
#pragma unroll
        for (int d = 0; d < 64; d++) mu += r[d];
        mu *= (1.f/64.f);
        float var = 0.f;
#pragma unroll
        for (int d = 0; d < 64; d++) { float t = r[d]-mu; var += t*t; }
        var *= (1.f/64.f);
        float inv = rsqrtf(var + 1e-5f);
#pragma unroll
        for (int d = 0; d < 64; d++)
            r[d] = (r[d]-mu)*inv*g3[d] + b3[d];
    }
    __syncthreads();

    if (tid < TD) {
        float s = 0.f;
        for (int nn = 0; nn < NT; ++nn) s += h2[nn*65 + tid];
        psm[tid] = s * (1.f/128.f);
    }
    __syncthreads();

    float val = 0.f;
    if (tid < 128) {
        float s = bf1[tid];
        for (int d = 0; d < TD; ++d)
            s = fmaf(psm[d], Wf1[d*128 + tid], s);
        s = fmaxf(s, 0.f);
        val = s * Wf2[tid];
    }
#pragma unroll
    for (int o = 16; o; o >>= 1)
        val += __shfl_xor_sync(0xffffffffu, val, o);
    if ((tid & 31) == 0) red[tid >> 5] = val;
    __syncthreads();
    if (tid == 0)
        out[b] = red[0] + red[1] + red[2] + red[3] + bf2[0];
}

// ---------------- launch ----------------
extern "C" void kernel_launch(void* const* d_in, const int* in_sizes, int n_in,
                              void* d_out, int out_size) {
    const float* x    = (const float*)d_in[0];
    const float* g1   = (const float*)d_in[1];
    const float* b1   = (const float*)d_in[2];
    const float* Wq   = (const float*)d_in[3];
    const float* bq   = (const float*)d_in[4];
    const float* Wk   = (const float*)d_in[5];
    const float* bk   = (const float*)d_in[6];
    const float* Wv   = (const float*)d_in[7];
    const float* bv   = (const float*)d_in[8];
    const float* Wo   = (const float*)d_in[9];
    const float* bo   = (const float*)d_in[10];
    const float* proj = (const float*)d_in[11];
    const float* g2   = (const float*)d_in[12];
    const float* b2   = (const float*)d_in[13];
    const float* W1   = (const float*)d_in[14];
    const float* c1   = (const float*)d_in[15];
    const float* W2   = (const float*)d_in[16];
    const float* c2   = (const float*)d_in[17];
    const float* g3   = (const float*)d_in[18];
    const float* b3   = (const float*)d_in[19];
    const float* Wf1  = (const float*)d_in[20];
    const float* bf1  = (const float*)d_in[21];
    const float* Wf2  = (const float*)d_in[22];
    const float* bf2  = (const float*)d_in[23];
    float* out = (float*)d_out;

    cudaFuncSetAttribute(kfeat,      cudaFuncAttributeMaxDynamicSharedMemorySize, KF_SMEM);
    cudaFuncSetAttribute(k2b_mma,    cudaFuncAttributeMaxDynamicSharedMemorySize, K2B_SMEM);
    cudaFuncSetAttribute(k3b_mma,    cudaFuncAttributeMaxDynamicSharedMemorySize, K3B_SMEM);
    cudaFuncSetAttribute(k4a_proj,   cudaFuncAttributeMaxDynamicSharedMemorySize, K4A_SMEM);
    cudaFuncSetAttribute(k4b_ff_head,cudaFuncAttributeMaxDynamicSharedMemorySize, K4B_SMEM);

    k_init<<<1, 1>>>();
    k1_ln_qkv<<<BB, 512>>>(x, g1, b1, Wq, bq, Wk, bk, Wv, bv);
    kfeat<<<BB*HH, 256, KF_SMEM>>>(proj);
    k2b_mma<<<BB*HH, 256, K2B_SMEM>>>();
    k3x_stats<<<BB*HH, 256>>>();
    k3b_mma<<<BB*HH, 512, K3B_SMEM>>>();
    k4a_proj<<<BB, 256, K4A_SMEM>>>(x, Wo, bo);
    k4b_ff_head<<<BB, 256, K4B_SMEM>>>(x, g2, b2, W1, c1, W2, c2,
                                       g3, b3, Wf1, bf1, Wf2, bf2, out);
}

// round 9
// speedup vs baseline: 2.1179x; 1.4866x over previous
#include <cuda_runtime.h>
#include <math.h>

#define BB 256
#define NT 128
#define TD 64
#define HH 8
#define DH 64
#define IN 512
#define MM 266
#define ES 272
#define FH 256

#define DN    0.35355339059327373f
#define RATIO 0.0613139076f
#define RE    6.13139076e-6f

__device__ float g_q[BB*HH*NT*DH];
__device__ float g_k[BB*HH*NT*DH];
__device__ float g_v[BB*HH*NT*DH];
__device__ float g_Ek[BB*HH*NT*ES];
__device__ float g_Eq[BB*HH*NT*ES];
__device__ float g_ctxT[BB*HH*DH*ES];
__device__ float g_ksumU[BB*HH*MM];
__device__ float g_vsum[BB*HH*DH];
__device__ float g_qdg[BB*HH*NT];
__device__ float g_Tn[BB*HH*NT];
__device__ float g_Emx[BB*HH*NT];
__device__ float g_csA[BB*HH*DH];
__device__ float g_kss[BB*HH];
__device__ float g_o[BB*NT*IN];
__device__ float g_t[BB*NT*TD];
__device__ unsigned g_kmax;

__device__ __forceinline__ unsigned enc_f(float f) {
    unsigned u = __float_as_uint(f);
    return (u & 0x80000000u) ? ~u : (u | 0x80000000u);
}
__device__ __forceinline__ float dec_f(unsigned k) {
    return (k & 0x80000000u) ? __uint_as_float(k & 0x7fffffffu)
                             : __uint_as_float(~k);
}
__device__ __forceinline__ float to_tf32(float x) {
    unsigned r;
    asm("cvt.rna.tf32.f32 %0, %1;" : "=r"(r) : "f"(x));
    return __uint_as_float(r);
}
__device__ __forceinline__ void mma_tf32(float& c0, float& c1, float& c2, float& c3,
                                         unsigned a0, unsigned a1, unsigned a2, unsigned a3,
                                         unsigned b0, unsigned b1)
{
    asm volatile(
        "mma.sync.aligned.m16n8k8.row.col.f32.tf32.tf32.f32 "
        "{%0,%1,%2,%3}, {%4,%5,%6,%7}, {%8,%9}, {%0,%1,%2,%3};"
        : "+f"(c0), "+f"(c1), "+f"(c2), "+f"(c3)
        : "r"(a0), "r"(a1), "r"(a2), "r"(a3), "r"(b0), "r"(b1));
}

__global__ void k_init() { g_kmax = 0u; }

// ---------------- k1_mma: LN1 + one QKV projection via tf32 mma ----------------
#define K1_ST 68
#define K1_SMEM ((NT*K1_ST + IN*K1_ST)*4)   /* 34816 + 139264 = 174080 */

__global__ __launch_bounds__(256, 1)
void k1_mma(const float* __restrict__ x,
            const float* __restrict__ g1, const float* __restrict__ b1,
            const float* __restrict__ Wq, const float* __restrict__ bq,
            const float* __restrict__ Wk, const float* __restrict__ bk,
            const float* __restrict__ Wv, const float* __restrict__ bv)
{
    extern __shared__ float sm[];
    float* hs = sm;                 // [128][68] tf32 LN output
    float* Ws = sm + NT*K1_ST;      // [512 j][68] transposed W, tf32

    int b = blockIdx.x, w = blockIdx.y, t = threadIdx.x;
    int wid = t >> 5, lane = t & 31;
    int g = lane >> 2, q = lane & 3;
    int rA = wid*16 + g, rB = rA + 8;

    const float* W    = (w == 0) ? Wq : (w == 1) ? Wk : Wv;
    const float* bias = (w == 0) ? bq : (w == 1) ? bk : bv;
    float* dst = ((w == 0) ? g_q : (w == 1) ? g_k : g_v) + (size_t)b*HH*NT*DH;

    const float* xb = x + (size_t)b*NT*TD;
    for (int i = t; i < NT*TD; i += 256)
        hs[(i >> 6)*K1_ST + (i & 63)] = xb[i];
    // W transpose: Ws[j][d] = W[d][j]
    for (int i = t; i < TD*IN; i += 256) {
        int d = i >> 9, j = i & 511;
        Ws[j*K1_ST + d] = to_tf32(W[i]);
    }
    __syncthreads();
    if (t < NT) {
        float* r = &hs[t*K1_ST];
        float mu = 0.f;
#pragma unroll
        for (int d = 0; d < 64; d++) mu += r[d];
        mu *= (1.f/64.f);
        float var = 0.f;
#pragma unroll
        for (int d = 0; d < 64; d++) { float v = r[d]-mu; var += v*v; }
        var *= (1.f/64.f);
        float inv = rsqrtf(var + 1e-5f);
#pragma unroll
        for (int d = 0; d < 64; d++)
            r[d] = to_tf32((r[d]-mu)*inv*g1[d] + b1[d]);
    }
    __syncthreads();

    unsigned a[8][4];
#pragma unroll
    for (int kc = 0; kc < 8; ++kc) {
        a[kc][0] = __float_as_uint(hs[rA*K1_ST + kc*8 + q]);
        a[kc][1] = __float_as_uint(hs[rB*K1_ST + kc*8 + q]);
        a[kc][2] = __float_as_uint(hs[rA*K1_ST + kc*8 + q + 4]);
        a[kc][3] = __float_as_uint(hs[rB*K1_ST + kc*8 + q + 4]);
    }

    for (int nc = 0; nc < 64; ++nc) {
        float c0=0.f, c1=0.f, c2=0.f, c3=0.f;
        const float* pb = Ws + (nc*8 + g)*K1_ST + q;
#pragma unroll
        for (int kc = 0; kc < 8; ++kc) {
            unsigned b0 = __float_as_uint(pb[kc*8]);
            unsigned b1r = __float_as_uint(pb[kc*8 + 4]);
            mma_tf32(c0, c1, c2, c3,
                     a[kc][0], a[kc][1], a[kc][2], a[kc][3], b0, b1r);
        }
        int j0 = nc*8 + 2*q;
        int head = j0 >> 6, doff = j0 & 63;
        float2 bb = *(const float2*)(bias + j0);
        float* dA = dst + ((size_t)head*NT + rA)*DH + doff;
        float* dB = dst + ((size_t)head*NT + rB)*DH + doff;
        *(float2*)dA = make_float2(c0 + bb.x, c1 + bb.y);
        *(float2*)dB = make_float2(c2 + bb.x, c3 + bb.y);
    }
}

// ---------------- kfeat: mma.sync tf32 feature maps ----------------
#define XS_ST 68
#define PS_ST 68
#define KF_SMEM ((ES*PS_ST + NT*XS_ST)*4)

__global__ __launch_bounds__(256, 2)
void kfeat(const float* __restrict__ proj)
{
    extern __shared__ float dsm[];
    float* Ps = dsm;
    float* Xs = Ps + ES*PS_ST;
    __shared__ float diag[NT];
    __shared__ unsigned s_smax;

    int bh = blockIdx.x, t = threadIdx.x;
    int wid = t >> 5, lane = t & 31;
    int g = lane >> 2, q = lane & 3;
    int r0 = wid*16;
    int rA = r0 + g, rB = r0 + g + 8;

    const float* kg = g_k + (size_t)bh*NT*DH;
    const float* qg = g_q + (size_t)bh*NT*DH;

    if (t == 0) s_smax = 0u;

    for (int i = t; i < ES*DH; i += 256) {
        int m = i >> 6, d = i & 63;
        Ps[m*PS_ST + d] = (m < MM) ? to_tf32(proj[m*64 + d]) : 0.f;
    }
    for (int i = t; i < NT*DH; i += 256) {
        int r = i >> 6, d = i & 63;
        Xs[r*XS_ST + d] = to_tf32(kg[i] * DN);
    }
    if (t < NT) {
        float s = 0.f;
#pragma unroll
        for (int d = 0; d < 64; d++) { float v = kg[t*64+d]*DN; s = fmaf(v,v,s); }
        diag[t] = 0.5f * s;
    }
    __syncthreads();

    // keys
    {
        unsigned a[8][4];
#pragma unroll
        for (int kc = 0; kc < 8; ++kc) {
            a[kc][0] = __float_as_uint(Xs[rA*XS_ST + kc*8 + q]);
            a[kc][1] = __float_as_uint(Xs[rB*XS_ST + kc*8 + q]);
            a[kc][2] = __float_as_uint(Xs[rA*XS_ST + kc*8 + q + 4]);
            a[kc][3] = __float_as_uint(Xs[rB*XS_ST + kc*8 + q + 4]);
        }
        float dgA = diag[rA], dgB = diag[rB];
        float* EA = g_Ek + ((size_t)bh*NT + rA)*ES;
        float* EB = g_Ek + ((size_t)bh*NT + rB)*ES;
        float dmax = -1e30f;

        for (int nc = 0; nc < 34; ++nc) {
            float c0=0.f, c1=0.f, c2=0.f, c3=0.f;
            const float* pb = Ps + (nc*8 + g)*PS_ST + q;
#pragma unroll
            for (int kc = 0; kc < 8; ++kc) {
                unsigned b0 = __float_as_uint(pb[kc*8]);
                unsigned b1 = __float_as_uint(pb[kc*8 + 4]);
                mma_tf32(c0, c1, c2, c3,
                         a[kc][0], a[kc][1], a[kc][2], a[kc][3], b0, b1);
            }
            int n0 = nc*8 + 2*q;
            bool v0 = (n0 < MM), v1 = (n0+1 < MM);
            if (v0) dmax = fmaxf(dmax, fmaxf(c0, c2));
            if (v1) dmax = fmaxf(dmax, fmaxf(c1, c3));
            *(float2*)(EA + n0) = make_float2(__expf(c0 - dgA), __expf(c1 - dgA));
            *(float2*)(EB + n0) = make_float2(__expf(c2 - dgB), __expf(c3 - dgB));
        }
#pragma unroll
        for (int o = 16; o; o >>= 1)
            dmax = fmaxf(dmax, __shfl_xor_sync(0xffffffffu, dmax, o));
        if (lane == 0) atomicMax(&s_smax, enc_f(dmax));
    }
    __syncthreads();
    if (t == 0) atomicMax(&g_kmax, s_smax);

    for (int i = t; i < NT*DH; i += 256) {
        int r = i >> 6, d = i & 63;
        Xs[r*XS_ST + d] = to_tf32(qg[i] * DN);
    }
    if (t < NT) {
        float s = 0.f;
#pragma unroll
        for (int d = 0; d < 64; d++) { float v = qg[t*64+d]*DN; s = fmaf(v,v,s); }
        g_qdg[(size_t)bh*NT + t] = 0.5f * s;
    }
    __syncthreads();

    // queries
    {
        unsigned a[8][4];
#pragma unroll
        for (int kc = 0; kc < 8; ++kc) {
            a[kc][0] = __float_as_uint(Xs[rA*XS_ST + kc*8 + q]);
            a[kc][1] = __float_as_uint(Xs[rB*XS_ST + kc*8 + q]);
            a[kc][2] = __float_as_uint(Xs[rA*XS_ST + kc*8 + q + 4]);
            a[kc][3] = __float_as_uint(Xs[rB*XS_ST + kc*8 + q + 4]);
        }
        float* EA = g_Eq + ((size_t)bh*NT + rA)*ES;
        float* EB = g_Eq + ((size_t)bh*NT + rB)*ES;
        float emxA = 0.f, emxB = 0.f;

        for (int nc = 0; nc < 34; ++nc) {
            float c0=0.f, c1=0.f, c2=0.f, c3=0.f;
            const float* pb = Ps + (nc*8 + g)*PS_ST + q;
#pragma unroll
            for (int kc = 0; kc < 8; ++kc) {
                unsigned b0 = __float_as_uint(pb[kc*8]);
                unsigned b1 = __float_as_uint(pb[kc*8 + 4]);
                mma_tf32(c0, c1, c2, c3,
                         a[kc][0], a[kc][1], a[kc][2], a[kc][3], b0, b1);
            }
            int n0 = nc*8 + 2*q;
            bool v0 = (n0 < MM), v1 = (n0+1 < MM);
            float e0 = __expf(c0), e1 = __expf(c1);
            float e2 = __expf(c2), e3 = __expf(c3);
            if (v0) { emxA = fmaxf(emxA, e0); emxB = fmaxf(emxB, e2); }
            if (v1) { emxA = fmaxf(emxA, e1); emxB = fmaxf(emxB, e3); }
            *(float2*)(EA + n0) = make_float2(e0, e1);
            *(float2*)(EB + n0) = make_float2(e2, e3);
        }
        emxA = fmaxf(emxA, __shfl_xor_sync(0xffffffffu, emxA, 1));
        emxA = fmaxf(emxA, __shfl_xor_sync(0xffffffffu, emxA, 2));
        emxB = fmaxf(emxB, __shfl_xor_sync(0xffffffffu, emxB, 1));
        emxB = fmaxf(emxB, __shfl_xor_sync(0xffffffffu, emxB, 2));
        if (q == 0) {
            g_Emx[(size_t)bh*NT + rA] = emxA;
            g_Emx[(size_t)bh*NT + rB] = emxB;
        }
    }
}

// ---------------- k2b_mma: ctxT = V^T @ Ek, ksum, vsum ----------------
#define EKT_ST 68
#define K2B_SMEM ((ES*EKT_ST + DH*EKT_ST)*4)

__global__ __launch_bounds__(256, 2)
void k2b_mma()
{
    extern __shared__ float sm[];
    float* EkTs = sm;
    float* Vts  = sm + ES*EKT_ST;

    int bh = blockIdx.x, t = threadIdx.x;
    int wid = t >> 5, lane = t & 31;
    int g = lane >> 2, q = lane & 3;
    int mtile = wid >> 1;
    int ntb = (wid & 1) * 17;

    const float* Ekg = g_Ek + (size_t)bh*NT*ES;
    const float* vg  = g_v  + (size_t)bh*NT*DH;

    float acc[17][4];
#pragma unroll
    for (int j = 0; j < 17; ++j) { acc[j][0]=0.f; acc[j][1]=0.f; acc[j][2]=0.f; acc[j][3]=0.f; }
    float ks0 = 0.f, ks1 = 0.f, vs_r = 0.f;

    for (int c = 0; c < 2; ++c) {
        int n0 = c*64;
        for (int i = t; i < 64*64; i += 256) {
            int n = i >> 6, d = i & 63;
            Vts[d*EKT_ST + n] = vg[(n0+n)*64 + d];
        }
        for (int i = t; i < 64*ES; i += 256) {
            int n = i / ES, m = i - n*ES;
            EkTs[m*EKT_ST + n] = Ekg[(size_t)(n0+n)*ES + m];
        }
        __syncthreads();

        {
            float s = 0.f;
            const float4* r4 = (const float4*)(EkTs + t*EKT_ST);
#pragma unroll
            for (int j = 0; j < 16; ++j) { float4 v = r4[j]; s += (v.x+v.y)+(v.z+v.w); }
            ks0 += s;
            if (t < 16) {
                float s2 = 0.f;
                const float4* r2 = (const float4*)(EkTs + (t+256)*EKT_ST);
#pragma unroll
                for (int j = 0; j < 16; ++j) { float4 v = r2[j]; s2 += (v.x+v.y)+(v.z+v.w); }
                ks1 += s2;
            }
            if (t < 64) {
                float sv = 0.f;
                const float4* rv = (const float4*)(Vts + t*EKT_ST);
#pragma unroll
                for (int j = 0; j < 16; ++j) { float4 v = rv[j]; sv += (v.x+v.y)+(v.z+v.w); }
                vs_r += sv;
            }
        }

#pragma unroll
        for (int ks = 0; ks < 8; ++ks) {
            unsigned a0 = __float_as_uint(Vts[(mtile*16+g)*EKT_ST + ks*8 + q]);
            unsigned a1 = __float_as_uint(Vts[(mtile*16+g+8)*EKT_ST + ks*8 + q]);
            unsigned a2 = __float_as_uint(Vts[(mtile*16+g)*EKT_ST + ks*8 + q + 4]);
            unsigned a3 = __float_as_uint(Vts[(mtile*16+g+8)*EKT_ST + ks*8 + q + 4]);
#pragma unroll
            for (int j = 0; j < 17; ++j) {
                int mrow = (ntb + j)*8 + g;
                unsigned b0 = __float_as_uint(EkTs[mrow*EKT_ST + ks*8 + q]);
                unsigned b1 = __float_as_uint(EkTs[mrow*EKT_ST + ks*8 + q + 4]);
                mma_tf32(acc[j][0], acc[j][1], acc[j][2], acc[j][3],
                         a0, a1, a2, a3, b0, b1);
            }
        }
        __syncthreads();
    }

    int dA = mtile*16 + g, dB = dA + 8;
    float* ctA = g_ctxT + ((size_t)bh*DH + dA)*ES;
    float* ctB = g_ctxT + ((size_t)bh*DH + dB)*ES;
#pragma unroll
    for (int j = 0; j < 17; ++j) {
        int m0 = (ntb + j)*8 + 2*q;
        float e0 = (m0   < MM) ? acc[j][0] : 0.f;
        float e1 = (m0+1 < MM) ? acc[j][1] : 0.f;
        float e2 = (m0   < MM) ? acc[j][2] : 0.f;
        float e3 = (m0+1 < MM) ? acc[j][3] : 0.f;
        *(float2*)(ctA + m0) = make_float2(e0, e1);
        *(float2*)(ctB + m0) = make_float2(e2, e3);
    }
    if (t < MM) g_ksumU[(size_t)bh*MM + t] = ks0;
    if (t < 16 && t + 256 < MM) g_ksumU[(size_t)bh*MM + t + 256] = ks1;
    if (t < DH) g_vsum[(size_t)bh*DH + t] = vs_r;
}

// ---------------- k3x: per-bh stats ----------------
__global__ __launch_bounds__(256, 4)
void k3x_stats()
{
    __shared__ float ksm[ES];
    int bh = blockIdx.x, t = threadIdx.x;
    int wid = t >> 5, lane = t & 31;
    float A = RATIO * __expf(-dec_f(g_kmax));
    for (int i = t; i < ES; i += 256)
        ksm[i] = (i < MM) ? fmaf(A, g_ksumU[(size_t)bh*MM + i], RE*128.f) : 0.f;
    __syncthreads();

    for (int j = 0; j < 8; ++j) {
        int d = wid*8 + j;
        const float* row = g_ctxT + ((size_t)bh*DH + d)*ES;
        float s = 0.f;
        for (int m = lane; m < MM; m += 32) s += row[m];
#pragma unroll
        for (int o = 16; o; o >>= 1) s += __shfl_xor_sync(0xffffffffu, s, o);
        if (lane == 0)
            g_csA[(size_t)bh*DH + d] = fmaf(A, s, (float)MM * RE * g_vsum[(size_t)bh*DH + d]);
    }
    if (wid == 0) {
        float s = 0.f;
        for (int i = lane; i < MM; i += 32) s += ksm[i];
#pragma unroll
        for (int o = 16; o; o >>= 1) s += __shfl_xor_sync(0xffffffffu, s, o);
        if (lane == 0) g_kss[bh] = s;
    }
    const float* Eb = g_Eq + (size_t)bh*NT*ES;
    for (int j = 0; j < 16; ++j) {
        int n = wid*16 + j;
        const float* er = Eb + (size_t)n*ES;
        float s = 0.f;
        for (int m = lane; m < MM; m += 32) s = fmaf(er[m], ksm[m], s);
#pragma unroll
        for (int o = 16; o; o >>= 1) s += __shfl_xor_sync(0xffffffffu, s, o);
        if (lane == 0) g_Tn[(size_t)bh*NT + n] = s;
    }
}

// ---------------- k3b_mma: O = Eq @ ctx_scaled + epilogue ----------------
#define EQ_ST 137
#define K3B_SMEM ((NT*EQ_ST + DH*EQ_ST)*4)

__global__ __launch_bounds__(512, 1)
void k3b_mma()
{
    extern __shared__ float sm[];
    float* Eqs   = sm;
    float* ctxTs = sm + NT*EQ_ST;
    __shared__ float qd_s[NT], Emx_s[NT], Tn_s[NT], cs_s[DH], vs_s[DH];
    __shared__ float sA, skss;

    int bh = blockIdx.x, t = threadIdx.x;
    int wid = t >> 5, lane = t & 31;
    int g = lane >> 2, q = lane & 3;
    int mtile = wid >> 1;
    int dbase = (wid & 1)*32;

    if (t == 0) { sA = RATIO * __expf(-dec_f(g_kmax)); skss = g_kss[bh]; }
    if (t < NT) {
        qd_s[t]  = g_qdg[(size_t)bh*NT + t];
        Emx_s[t] = g_Emx[(size_t)bh*NT + t];
        Tn_s[t]  = g_Tn[(size_t)bh*NT + t];
    }
    if (t < DH) {
        cs_s[t] = g_csA[(size_t)bh*DH + t];
        vs_s[t] = g_vsum[(size_t)bh*DH + t];
    }
    __syncthreads();
    float A = sA;

    const float* Eqg = g_Eq + (size_t)bh*NT*ES;
    const float* ctg = g_ctxT + (size_t)bh*DH*ES;

    float acc[4][4];
#pragma unroll
    for (int j = 0; j < 4; ++j) { acc[j][0]=0.f; acc[j][1]=0.f; acc[j][2]=0.f; acc[j][3]=0.f; }

    for (int c = 0; c < 2; ++c) {
        int m0 = c*136;
        for (int i = t; i < NT*136; i += 512) {
            int r = i / 136, cc = i - r*136;
            Eqs[r*EQ_ST + cc] = Eqg[(size_t)r*ES + m0 + cc];
        }
        for (int i = t; i < DH*136; i += 512) {
            int d = i / 136, cc = i - d*136;
            int mg = m0 + cc;
            float raw = ctg[(size_t)d*ES + mg];
            ctxTs[d*EQ_ST + cc] = (mg < MM) ? fmaf(A, raw, RE*vs_s[d]) : 0.f;
        }
        __syncthreads();

#pragma unroll
        for (int ks = 0; ks < 17; ++ks) {
            unsigned a0 = __float_as_uint(Eqs[(mtile*16+g)*EQ_ST + ks*8 + q]);
            unsigned a1 = __float_as_uint(Eqs[(mtile*16+g+8)*EQ_ST + ks*8 + q]);
            unsigned a2 = __float_as_uint(Eqs[(mtile*16+g)*EQ_ST + ks*8 + q + 4]);
            unsigned a3 = __float_as_uint(Eqs[(mtile*16+g+8)*EQ_ST + ks*8 + q + 4]);
#pragma unroll
            for (int nt = 0; nt < 4; ++nt) {
                int drow = dbase + nt*8 + g;
                unsigned b0 = __float_as_uint(ctxTs[drow*EQ_ST + ks*8 + q]);
                unsigned b1 = __float_as_uint(ctxTs[drow*EQ_ST + ks*8 + q + 4]);
                mma_tf32(acc[nt][0], acc[nt][1], acc[nt][2], acc[nt][3],
                         a0, a1, a2, a3, b0, b1);
            }
        }
        __syncthreads();
    }

    int rA = mtile*16 + g, rB = rA + 8;
    float rqA = RATIO * __expf(-qd_s[rA]) / Emx_s[rA];
    float rqB = RATIO * __expf(-qd_s[rB]) / Emx_s[rB];
    float kss = skss;
    float invA = 1.0f / fmaf(rqA, Tn_s[rA], RE*kss);
    float invB = 1.0f / fmaf(rqB, Tn_s[rB], RE*kss);
    int b = bh >> 3, h = bh & 7;
    float* oA = g_o + ((size_t)(b*NT + rA))*IN + h*DH;
    float* oB = g_o + ((size_t)(b*NT + rB))*IN + h*DH;
#pragma unroll
    for (int nt = 0; nt < 4; ++nt) {
        int d = dbase + nt*8 + 2*q;
        float2 vA, vB;
        vA.x = fmaf(rqA, acc[nt][0], RE*cs_s[d  ])*invA;
        vA.y = fmaf(rqA, acc[nt][1], RE*cs_s[d+1])*invA;
        vB.x = fmaf(rqB, acc[nt][2], RE*cs_s[d  ])*invB;
        vB.y = fmaf(rqB, acc[nt][3], RE*cs_s[d+1])*invB;
        *(float2*)(oA + d) = vA;
        *(float2*)(oB + d) = vB;
    }
}

// ---------------- k4a_mma: t = x + o @ Wo + bo (tf32 mma) ----------------
#define K4A_ST 132
#define K4A_SMEM ((NT*K4A_ST + DH*K4A_ST)*4)   /* 67584 + 33792 = 101376 */

__global__ __launch_bounds__(256, 2)
void k4a_mma(const float* __restrict__ x,
             const float* __restrict__ Wo, const float* __restrict__ bo)
{
    extern __shared__ float sm[];
    float* Os = sm;                 // [128][128+pad]
    float* Ws = sm + NT*K4A_ST;     // [64 d][128 k]

    int b = blockIdx.x, t = threadIdx.x;
    int wid = t >> 5, lane = t & 31;
    int g = lane >> 2, q = lane & 3;
    int rA = wid*16 + g, rB = rA + 8;

    float acc[8][4];
#pragma unroll
    for (int j = 0; j < 8; ++j) { acc[j][0]=0.f; acc[j][1]=0.f; acc[j][2]=0.f; acc[j][3]=0.f; }

    const float* ob = g_o + (size_t)b*NT*IN;

    for (int c = 0; c < 4; ++c) {
        int k0 = c*128;
        for (int i = t; i < NT*128; i += 256) {
            int r = i >> 7, kc = i & 127;
            Os[r*K4A_ST + kc] = to_tf32(ob[(size_t)r*IN + k0 + kc]);
        }
        for (int i = t; i < DH*128; i += 256) {
            int k = i >> 6, d = i & 63;
            Ws[d*K4A_ST + k] = to_tf32(Wo[(size_t)(k0+k)*TD + d]);
        }
        __syncthreads();

#pragma unroll
        for (int ks = 0; ks < 16; ++ks) {
            unsigned a0 = __float_as_uint(Os[rA*K4A_ST + ks*8 + q]);
            unsigned a1 = __float_as_uint(Os[rB*K4A_ST + ks*8 + q]);
            unsigned a2 = __float_as_uint(Os[rA*K4A_ST + ks*8 + q + 4]);
            unsigned a3 = __float_as_uint(Os[rB*K4A_ST + ks*8 + q + 4]);
#pragma unroll
            for (int nt = 0; nt < 8; ++nt) {
                int drow = nt*8 + g;
                unsigned b0 = __float_as_uint(Ws[drow*K4A_ST + ks*8 + q]);
                unsigned b1 = __float_as_uint(Ws[drow*K4A_ST + ks*8 + q + 4]);
                mma_tf32(acc[nt][0], acc[nt][1], acc[nt][2], acc[nt][3],
                         a0, a1, a2, a3, b0, b1);
            }
        }
        __syncthreads();
    }

    const float* xb = x + (size_t)b*NT*TD;
    float* tb = g_t + (size_t)b*NT*TD;
#pragma unroll
    for (int nt = 0; nt < 8; ++nt) {
        int d = nt*8 + 2*q;
        float2 bb = *(const float2*)(bo + d);
        float2 xA = *(const float2*)(xb + rA*TD + d);
        float2 xB = *(const float2*)(xb + rB*TD + d);
        *(float2*)(tb + rA*TD + d) =
            make_float2(acc[nt][0] + bb.x + xA.x, acc[nt][1] + bb.y + xA.y);
        *(float2*)(tb + rB*TD + d) =
            make_float2(acc[nt][2] + bb.x + xB.x, acc[nt][3] + bb.y + xB.y);
    }
}

// ---------------- K4b ----------------
#define K4B_SMEM ((NT*65 + NT*FH + TD*FH + 64 + 16)*4)

__global__ __launch_bounds__(256, 1)
void k4b_ff_head(const float* __restrict__ x,
                 const float* __restrict__ g2, const float* __restrict__ b2,
                 const float* __restrict__ W1, const float* __restrict__ c1,
                 const float* __restrict__ W2, const float* __restrict__ c2,
                 const float* __restrict__ g3, const float* __restrict__ b3,
                 const float* __restrict__ Wf1, const float* __restrict__ bf1,
                 const float* __restrict__ Wf2, const float* __restrict__ bf2,
                 float* __restrict__ out)
{
    extern __shared__ float sm4[];
    float* h2  = sm4;
    float* gsm = h2 + NT*65;
    float* wsm = gsm + NT*FH;
    float* psm = wsm + TD*FH;
    float* red = psm + 64;

    int b = blockIdx.x, tid = threadIdx.x;

    if (tid < NT) {
        const float* tr = g_t + ((size_t)(b*NT + tid))*TD;
        float tv[64];
#pragma unroll
        for (int j = 0; j < 16; ++j) {
            float4 t4 = *(const float4*)(tr + 4*j);
            tv[4*j]=t4.x; tv[4*j+1]=t4.y; tv[4*j+2]=t4.z; tv[4*j+3]=t4.w;
        }
        float mu = 0.f;
#pragma unroll
        for (int d = 0; d < 64; d++) mu += tv[d];
        mu *= (1.f/64.f);
        float var = 0.f;
#pragma unroll
        for (int d = 0; d < 64; d++) { float t = tv[d]-mu; var += t*t; }
        var *= (1.f/64.f);
        float inv = rsqrtf(var + 1e-5f);
#pragma unroll
        for (int d = 0; d < 64; d++)
            h2[tid*65 + d] = (tv[d]-mu)*inv*g2[d] + b2[d];
    }
    for (int i = tid; i < TD*FH; i += 256) wsm[i] = W1[i];
    __syncthreads();

    {
        int pt = tid & 63, grp = tid >> 6;
        int p4 = pt*4;
        float4 c14 = *(const float4*)(c1 + p4);
        for (int nn = grp; nn < NT; nn += 4) {
            float4 a = c14;
#pragma unroll
            for (int j = 0; j < TD; ++j) {
                float hv = h2[nn*65 + j];
                float4 w = *(float4*)&wsm[j*FH + p4];
                a.x = fmaf(hv, w.x, a.x); a.y = fmaf(hv, w.y, a.y);
                a.z = fmaf(hv, w.z, a.z); a.w = fmaf(hv, w.w, a.w);
            }
            a.x = 0.5f*a.x*(1.f + erff(a.x*0.70710678f));
            a.y = 0.5f*a.y*(1.f + erff(a.y*0.70710678f));
            a.z = 0.5f*a.z*(1.f + erff(a.z*0.70710678f));
            a.w = 0.5f*a.w*(1.f + erff(a.w*0.70710678f));
            *(float4*)&gsm[nn*FH + p4] = a;
        }
    }
    __syncthreads();
    for (int i = tid; i < FH*TD; i += 256) wsm[i] = W2[i];
    __syncthreads();

    {
        int jt = tid & 15, grp = tid >> 4;
        int j4 = jt*4;
        float4 c24 = *(const float4*)(c2 + j4);
        for (int nn = grp; nn < NT; nn += 16) {
            float4 a = c24;
            for (int p = 0; p < FH; ++p) {
                float gv = gsm[nn*FH + p];
                float4 w = *(float4*)&wsm[p*64 + j4];
                a.x = fmaf(gv, w.x, a.x); a.y = fmaf(gv, w.y, a.y);
                a.z = fmaf(gv, w.z, a.z); a.w = fmaf(gv, w.w, a.w);
            }
            float4 t4 = *(const float4*)(g_t + (size_t)b*NT*TD + nn*TD + j4);
            float4 x4 = *(const float4*)(x   + (size_t)b*NT*TD + nn*TD + j4);
            h2[nn*65 + j4 + 0] = a.x + t4.x + x4.x;
            h2[nn*65 + j4 + 1] = a.y + t4.y + x4.y;
            h2[nn*65 + j4 + 2] = a.z + t4.z + x4.z;
            h2[nn*65 + j4 + 3] = a.w + t4.w + x4.w;
        }
    }
    __syncthreads();

    if (tid < NT) {
        float* r = &h2[tid*65];
        float mu = 0.f;
#pragma unroll
        for (int d = 0; d < 64; d++) mu += r[d];
        mu *= (1.f/64.f);
        float var = 0.f;
#pragma unroll
        for (int d = 0; d < 64; d++) { float t = r[d]-mu; var += t*t; }
        var *= (1.f/64.f);
        float inv = rsqrtf(var + 1e-5f);
#pragma unroll
        for (int d = 0; d < 64; d++)
            r[d] = (r[d]-mu)*inv*g3[d] + b3[d];
    }
    __syncthreads();

    if (tid < TD) {
        float s = 0.f;
        for (int nn = 0; nn < NT; ++nn) s += h2[nn*65 + tid];
        psm[tid] = s * (1.f/128.f);
    }
    __syncthreads();

    float val = 0.f;
    if (tid < 128) {
        float s = bf1[tid];
        for (int d = 0; d < TD; ++d)
            s = fmaf(psm[d], Wf1[d*128 + tid], s);
        s = fmaxf(s, 0.f);
        val = s * Wf2[tid];
    }
#pragma unroll
    for (int o = 16; o; o >>= 1)
        val += __shfl_xor_sync(0xffffffffu, val, o);
    if ((tid & 31) == 0) red[tid >> 5] = val;
    __syncthreads();
    if (tid == 0)
        out[b] = red[0] + red[1] + red[2] + red[3] + bf2[0];
}

// ---------------- launch ----------------
extern "C" void kernel_launch(void* const* d_in, const int* in_sizes, int n_in,
                              void* d_out, int out_size) {
    const float* x    = (const float*)d_in[0];
    const float* g1   = (const float*)d_in[1];
    const float* b1   = (const float*)d_in[2];
    const float* Wq   = (const float*)d_in[3];
    const float* bq   = (const float*)d_in[4];
    const float* Wk   = (const float*)d_in[5];
    const float* bk   = (const float*)d_in[6];
    const float* Wv   = (const float*)d_in[7];
    const float* bv   = (const float*)d_in[8];
    const float* Wo   = (const float*)d_in[9];
    const float* bo   = (const float*)d_in[10];
    const float* proj = (const float*)d_in[11];
    const float* g2   = (const float*)d_in[12];
    const float* b2   = (const float*)d_in[13];
    const float* W1   = (const float*)d_in[14];
    const float* c1   = (const float*)d_in[15];
    const float* W2   = (const float*)d_in[16];
    const float* c2   = (const float*)d_in[17];
    const float* g3   = (const float*)d_in[18];
    const float* b3   = (const float*)d_in[19];
    const float* Wf1  = (const float*)d_in[20];
    const float* bf1  = (const float*)d_in[21];
    const float* Wf2  = (const float*)d_in[22];
    const float* bf2  = (const float*)d_in[23];
    float* out = (float*)d_out;

    cudaFuncSetAttribute(k1_mma,     cudaFuncAttributeMaxDynamicSharedMemorySize, K1_SMEM);
    cudaFuncSetAttribute(kfeat,      cudaFuncAttributeMaxDynamicSharedMemorySize, KF_SMEM);
    cudaFuncSetAttribute(k2b_mma,    cudaFuncAttributeMaxDynamicSharedMemorySize, K2B_SMEM);
    cudaFuncSetAttribute(k3b_mma,    cudaFuncAttributeMaxDynamicSharedMemorySize, K3B_SMEM);
    cudaFuncSetAttribute(k4a_mma,    cudaFuncAttributeMaxDynamicSharedMemorySize, K4A_SMEM);
    cudaFuncSetAttribute(k4b_ff_head,cudaFuncAttributeMaxDynamicSharedMemorySize, K4B_SMEM);

    k_init<<<1, 1>>>();
    k1_mma<<<dim3(BB, 3), 256, K1_SMEM>>>(x, g1, b1, Wq, bq, Wk, bk, Wv, bv);
    kfeat<<<BB*HH, 256, KF_SMEM>>>(proj);
    k2b_mma<<<BB*HH, 256, K2B_SMEM>>>();
    k3x_stats<<<BB*HH, 256>>>();
    k3b_mma<<<BB*HH, 512, K3B_SMEM>>>();
    k4a_mma<<<BB, 256, K4A_SMEM>>>(x, Wo, bo);
    k4b_ff_head<<<BB, 256, K4B_SMEM>>>(x, g2, b2, W1, c1, W2, c2,
                                       g3, b3, Wf1, bf1, Wf2, bf2, out);
}

// round 10
// speedup vs baseline: 2.3366x; 1.1033x over previous
#include <cuda_runtime.h>
#include <math.h>

#define BB 256
#define NT 128
#define TD 64
#define HH 8
#define DH 64
#define IN 512
#define MM 266
#define ES 272
#define FH 256

#define DN    0.35355339059327373f
#define RATIO 0.0613139076f
#define RE    6.13139076e-6f

__device__ float g_q[BB*HH*NT*DH];
__device__ float g_k[BB*HH*NT*DH];
__device__ float g_v[BB*HH*NT*DH];
__device__ float g_Ek[BB*HH*NT*ES];
__device__ float g_Eq[BB*HH*NT*ES];
__device__ float g_ctxT[BB*HH*DH*ES];
__device__ float g_ksumU[BB*HH*MM];
__device__ float g_vsum[BB*HH*DH];
__device__ float g_qdg[BB*HH*NT];
__device__ float g_Emx[BB*HH*NT];
__device__ float g_csA[BB*HH*DH];
__device__ float g_kss[BB*HH];
__device__ float g_o[BB*NT*IN];
__device__ float g_t[BB*NT*TD];
__device__ float g_ff[BB*NT*FH];
__device__ unsigned g_kmax;

__device__ __forceinline__ unsigned enc_f(float f) {
    unsigned u = __float_as_uint(f);
    return (u & 0x80000000u) ? ~u : (u | 0x80000000u);
}
__device__ __forceinline__ float dec_f(unsigned k) {
    return (k & 0x80000000u) ? __uint_as_float(k & 0x7fffffffu)
                             : __uint_as_float(~k);
}
__device__ __forceinline__ float to_tf32(float x) {
    unsigned r;
    asm("cvt.rna.tf32.f32 %0, %1;" : "=r"(r) : "f"(x));
    return __uint_as_float(r);
}
__device__ __forceinline__ void mma_tf32(float& c0, float& c1, float& c2, float& c3,
                                         unsigned a0, unsigned a1, unsigned a2, unsigned a3,
                                         unsigned b0, unsigned b1)
{
    asm volatile(
        "mma.sync.aligned.m16n8k8.row.col.f32.tf32.tf32.f32 "
        "{%0,%1,%2,%3}, {%4,%5,%6,%7}, {%8,%9}, {%0,%1,%2,%3};"
        : "+f"(c0), "+f"(c1), "+f"(c2), "+f"(c3)
        : "r"(a0), "r"(a1), "r"(a2), "r"(a3), "r"(b0), "r"(b1));
}

__global__ void k_init() { g_kmax = 0u; }

// ---------------- k1_mma: LN1 + one QKV projection ----------------
#define K1_ST 68
#define K1_SMEM ((NT*K1_ST + IN*K1_ST)*4)

__global__ __launch_bounds__(256, 1)
void k1_mma(const float* __restrict__ x,
            const float* __restrict__ g1, const float* __restrict__ b1,
            const float* __restrict__ Wq, const float* __restrict__ bq,
            const float* __restrict__ Wk, const float* __restrict__ bk,
            const float* __restrict__ Wv, const float* __restrict__ bv)
{
    extern __shared__ float sm[];
    float* hs = sm;
    float* Ws = sm + NT*K1_ST;

    int b = blockIdx.x, w = blockIdx.y, t = threadIdx.x;
    int wid = t >> 5, lane = t & 31;
    int g = lane >> 2, q = lane & 3;
    int rA = wid*16 + g, rB = rA + 8;

    const float* W    = (w == 0) ? Wq : (w == 1) ? Wk : Wv;
    const float* bias = (w == 0) ? bq : (w == 1) ? bk : bv;
    float* dst = ((w == 0) ? g_q : (w == 1) ? g_k : g_v) + (size_t)b*HH*NT*DH;

    const float* xb = x + (size_t)b*NT*TD;
    for (int i = t; i < NT*TD; i += 256)
        hs[(i >> 6)*K1_ST + (i & 63)] = xb[i];
    for (int i = t; i < TD*IN; i += 256) {
        int d = i >> 9, j = i & 511;
        Ws[j*K1_ST + d] = to_tf32(W[i]);
    }
    __syncthreads();
    if (t < NT) {
        float* r = &hs[t*K1_ST];
        float mu = 0.f;
#pragma unroll
        for (int d = 0; d < 64; d++) mu += r[d];
        mu *= (1.f/64.f);
        float var = 0.f;
#pragma unroll
        for (int d = 0; d < 64; d++) { float v = r[d]-mu; var += v*v; }
        var *= (1.f/64.f);
        float inv = rsqrtf(var + 1e-5f);
#pragma unroll
        for (int d = 0; d < 64; d++)
            r[d] = to_tf32((r[d]-mu)*inv*g1[d] + b1[d]);
    }
    __syncthreads();

    unsigned a[8][4];
#pragma unroll
    for (int kc = 0; kc < 8; ++kc) {
        a[kc][0] = __float_as_uint(hs[rA*K1_ST + kc*8 + q]);
        a[kc][1] = __float_as_uint(hs[rB*K1_ST + kc*8 + q]);
        a[kc][2] = __float_as_uint(hs[rA*K1_ST + kc*8 + q + 4]);
        a[kc][3] = __float_as_uint(hs[rB*K1_ST + kc*8 + q + 4]);
    }

    for (int nc = 0; nc < 64; ++nc) {
        float c0=0.f, c1=0.f, c2=0.f, c3=0.f;
        const float* pb = Ws + (nc*8 + g)*K1_ST + q;
#pragma unroll
        for (int kc = 0; kc < 8; ++kc) {
            unsigned b0 = __float_as_uint(pb[kc*8]);
            unsigned b1r = __float_as_uint(pb[kc*8 + 4]);
            mma_tf32(c0, c1, c2, c3,
                     a[kc][0], a[kc][1], a[kc][2], a[kc][3], b0, b1r);
        }
        int j0 = nc*8 + 2*q;
        int head = j0 >> 6, doff = j0 & 63;
        float2 bb = *(const float2*)(bias + j0);
        float* dA = dst + ((size_t)head*NT + rA)*DH + doff;
        float* dB = dst + ((size_t)head*NT + rB)*DH + doff;
        *(float2*)dA = make_float2(c0 + bb.x, c1 + bb.y);
        *(float2*)dB = make_float2(c2 + bb.x, c3 + bb.y);
    }
}

// ---------------- kfeat ----------------
#define XS_ST 68
#define PS_ST 68
#define KF_SMEM ((ES*PS_ST + NT*XS_ST)*4)

__global__ __launch_bounds__(256, 2)
void kfeat(const float* __restrict__ proj)
{
    extern __shared__ float dsm[];
    float* Ps = dsm;
    float* Xs = Ps + ES*PS_ST;
    __shared__ float diag[NT];
    __shared__ unsigned s_smax;

    int bh = blockIdx.x, t = threadIdx.x;
    int wid = t >> 5, lane = t & 31;
    int g = lane >> 2, q = lane & 3;
    int r0 = wid*16;
    int rA = r0 + g, rB = r0 + g + 8;

    const float* kg = g_k + (size_t)bh*NT*DH;
    const float* qg = g_q + (size_t)bh*NT*DH;

    if (t == 0) s_smax = 0u;

    for (int i = t; i < ES*DH; i += 256) {
        int m = i >> 6, d = i & 63;
        Ps[m*PS_ST + d] = (m < MM) ? to_tf32(proj[m*64 + d]) : 0.f;
    }
    for (int i = t; i < NT*DH; i += 256) {
        int r = i >> 6, d = i & 63;
        Xs[r*XS_ST + d] = to_tf32(kg[i] * DN);
    }
    if (t < NT) {
        float s = 0.f;
#pragma unroll
        for (int d = 0; d < 64; d++) { float v = kg[t*64+d]*DN; s = fmaf(v,v,s); }
        diag[t] = 0.5f * s;
    }
    __syncthreads();

    // keys
    {
        unsigned a[8][4];
#pragma unroll
        for (int kc = 0; kc < 8; ++kc) {
            a[kc][0] = __float_as_uint(Xs[rA*XS_ST + kc*8 + q]);
            a[kc][1] = __float_as_uint(Xs[rB*XS_ST + kc*8 + q]);
            a[kc][2] = __float_as_uint(Xs[rA*XS_ST + kc*8 + q + 4]);
            a[kc][3] = __float_as_uint(Xs[rB*XS_ST + kc*8 + q + 4]);
        }
        float dgA = diag[rA], dgB = diag[rB];
        float* EA = g_Ek + ((size_t)bh*NT + rA)*ES;
        float* EB = g_Ek + ((size_t)bh*NT + rB)*ES;
        float dmax = -1e30f;

        for (int nc = 0; nc < 34; ++nc) {
            float c0=0.f, c1=0.f, c2=0.f, c3=0.f;
            const float* pb = Ps + (nc*8 + g)*PS_ST + q;
#pragma unroll
            for (int kc = 0; kc < 8; ++kc) {
                unsigned b0 = __float_as_uint(pb[kc*8]);
                unsigned b1 = __float_as_uint(pb[kc*8 + 4]);
                mma_tf32(c0, c1, c2, c3,
                         a[kc][0], a[kc][1], a[kc][2], a[kc][3], b0, b1);
            }
            int n0 = nc*8 + 2*q;
            bool v0 = (n0 < MM), v1 = (n0+1 < MM);
            if (v0) dmax = fmaxf(dmax, fmaxf(c0, c2));
            if (v1) dmax = fmaxf(dmax, fmaxf(c1, c3));
            *(float2*)(EA + n0) = make_float2(__expf(c0 - dgA), __expf(c1 - dgA));
            *(float2*)(EB + n0) = make_float2(__expf(c2 - dgB), __expf(c3 - dgB));
        }
#pragma unroll
        for (int o = 16; o; o >>= 1)
            dmax = fmaxf(dmax, __shfl_xor_sync(0xffffffffu, dmax, o));
        if (lane == 0) atomicMax(&s_smax, enc_f(dmax));
    }
    __syncthreads();
    if (t == 0) atomicMax(&g_kmax, s_smax);

    for (int i = t; i < NT*DH; i += 256) {
        int r = i >> 6, d = i & 63;
        Xs[r*XS_ST + d] = to_tf32(qg[i] * DN);
    }
    if (t < NT) {
        float s = 0.f;
#pragma unroll
        for (int d = 0; d < 64; d++) { float v = qg[t*64+d]*DN; s = fmaf(v,v,s); }
        g_qdg[(size_t)bh*NT + t] = 0.5f * s;
    }
    __syncthreads();

    // queries
    {
        unsigned a[8][4];
#pragma unroll
        for (int kc = 0; kc < 8; ++kc) {
            a[kc][0] = __float_as_uint(Xs[rA*XS_ST + kc*8 + q]);
            a[kc][1] = __float_as_uint(Xs[rB*XS_ST + kc*8 + q]);
            a[kc][2] = __float_as_uint(Xs[rA*XS_ST + kc*8 + q + 4]);
            a[kc][3] = __float_as_uint(Xs[rB*XS_ST + kc*8 + q + 4]);
        }
        float* EA = g_Eq + ((size_t)bh*NT + rA)*ES;
        float* EB = g_Eq + ((size_t)bh*NT + rB)*ES;
        float emxA = 0.f, emxB = 0.f;

        for (int nc = 0; nc < 34; ++nc) {
            float c0=0.f, c1=0.f, c2=0.f, c3=0.f;
            const float* pb = Ps + (nc*8 + g)*PS_ST + q;
#pragma unroll
            for (int kc = 0; kc < 8; ++kc) {
                unsigned b0 = __float_as_uint(pb[kc*8]);
                unsigned b1 = __float_as_uint(pb[kc*8 + 4]);
                mma_tf32(c0, c1, c2, c3,
                         a[kc][0], a[kc][1], a[kc][2], a[kc][3], b0, b1);
            }
            int n0 = nc*8 + 2*q;
            bool v0 = (n0 < MM), v1 = (n0+1 < MM);
            float e0 = __expf(c0), e1 = __expf(c1);
            float e2 = __expf(c2), e3 = __expf(c3);
            if (v0) { emxA = fmaxf(emxA, e0); emxB = fmaxf(emxB, e2); }
            if (v1) { emxA = fmaxf(emxA, e1); emxB = fmaxf(emxB, e3); }
            *(float2*)(EA + n0) = make_float2(e0, e1);
            *(float2*)(EB + n0) = make_float2(e2, e3);
        }
        emxA = fmaxf(emxA, __shfl_xor_sync(0xffffffffu, emxA, 1));
        emxA = fmaxf(emxA, __shfl_xor_sync(0xffffffffu, emxA, 2));
        emxB = fmaxf(emxB, __shfl_xor_sync(0xffffffffu, emxB, 1));
        emxB = fmaxf(emxB, __shfl_xor_sync(0xffffffffu, emxB, 2));
        if (q == 0) {
            g_Emx[(size_t)bh*NT + rA] = emxA;
            g_Emx[(size_t)bh*NT + rB] = emxB;
        }
    }
}

// ---------------- k2b_mma: ctxT = V^T @ Ek + ksum/vsum/csA/kss ----------------
#define EKT_ST 68
#define K2B_SMEM ((ES*EKT_ST + DH*EKT_ST)*4)

__global__ __launch_bounds__(256, 2)
void k2b_mma()
{
    extern __shared__ float sm[];
    float* EkTs = sm;
    float* Vts  = sm + ES*EKT_ST;
    __shared__ float csp[2][64];
    __shared__ float redk[8];

    int bh = blockIdx.x, t = threadIdx.x;
    int wid = t >> 5, lane = t & 31;
    int g = lane >> 2, q = lane & 3;
    int mtile = wid >> 1;
    int w2 = wid & 1;
    int ntb = w2 * 17;

    const float* Ekg = g_Ek + (size_t)bh*NT*ES;
    const float* vg  = g_v  + (size_t)bh*NT*DH;

    float acc[17][4];
#pragma unroll
    for (int j = 0; j < 17; ++j) { acc[j][0]=0.f; acc[j][1]=0.f; acc[j][2]=0.f; acc[j][3]=0.f; }
    float ks0 = 0.f, ks1 = 0.f, vs_r = 0.f;

    for (int c = 0; c < 2; ++c) {
        int n0 = c*64;
        for (int i = t; i < 64*64; i += 256) {
            int n = i >> 6, d = i & 63;
            Vts[d*EKT_ST + n] = vg[(n0+n)*64 + d];
        }
        for (int i = t; i < 64*ES; i += 256) {
            int n = i / ES, m = i - n*ES;
            EkTs[m*EKT_ST + n] = Ekg[(size_t)(n0+n)*ES + m];
        }
        __syncthreads();

        {
            float s = 0.f;
            const float4* r4 = (const float4*)(EkTs + t*EKT_ST);
#pragma unroll
            for (int j = 0; j < 16; ++j) { float4 v = r4[j]; s += (v.x+v.y)+(v.z+v.w); }
            ks0 += s;
            if (t < 16) {
                float s2 = 0.f;
                const float4* r2 = (const float4*)(EkTs + (t+256)*EKT_ST);
#pragma unroll
                for (int j = 0; j < 16; ++j) { float4 v = r2[j]; s2 += (v.x+v.y)+(v.z+v.w); }
                ks1 += s2;
            }
            if (t < 64) {
                float sv = 0.f;
                const float4* rv = (const float4*)(Vts + t*EKT_ST);
#pragma unroll
                for (int j = 0; j < 16; ++j) { float4 v = rv[j]; sv += (v.x+v.y)+(v.z+v.w); }
                vs_r += sv;
            }
        }

#pragma unroll
        for (int ks = 0; ks < 8; ++ks) {
            unsigned a0 = __float_as_uint(Vts[(mtile*16+g)*EKT_ST + ks*8 + q]);
            unsigned a1 = __float_as_uint(Vts[(mtile*16+g+8)*EKT_ST + ks*8 + q]);
            unsigned a2 = __float_as_uint(Vts[(mtile*16+g)*EKT_ST + ks*8 + q + 4]);
            unsigned a3 = __float_as_uint(Vts[(mtile*16+g+8)*EKT_ST + ks*8 + q + 4]);
#pragma unroll
            for (int j = 0; j < 17; ++j) {
                int mrow = (ntb + j)*8 + g;
                unsigned b0 = __float_as_uint(EkTs[mrow*EKT_ST + ks*8 + q]);
                unsigned b1 = __float_as_uint(EkTs[mrow*EKT_ST + ks*8 + q + 4]);
                mma_tf32(acc[j][0], acc[j][1], acc[j][2], acc[j][3],
                         a0, a1, a2, a3, b0, b1);
            }
        }
        __syncthreads();
    }

    float A = RATIO * __expf(-dec_f(g_kmax));
    int dA = mtile*16 + g, dB = dA + 8;

    // csA partials from live accumulators
    {
        float pA = 0.f, pB = 0.f;
#pragma unroll
        for (int j = 0; j < 17; ++j) {
            int m0 = (ntb + j)*8 + 2*q;
            if (m0   < MM) { pA += acc[j][0]; pB += acc[j][2]; }
            if (m0+1 < MM) { pA += acc[j][1]; pB += acc[j][3]; }
        }
        pA += __shfl_xor_sync(0xffffffffu, pA, 1);
        pA += __shfl_xor_sync(0xffffffffu, pA, 2);
        pB += __shfl_xor_sync(0xffffffffu, pB, 1);
        pB += __shfl_xor_sync(0xffffffffu, pB, 2);
        if (q == 0) { csp[w2][dA] = pA; csp[w2][dB] = pB; }
    }

    // kss reduction
    {
        float kt = (t < MM) ? ks0 : 0.f;
        if (t < 16 && t + 256 < MM) kt += ks1;
#pragma unroll
        for (int o = 16; o; o >>= 1) kt += __shfl_xor_sync(0xffffffffu, kt, o);
        if (lane == 0) redk[wid] = kt;
    }

    float* ctA = g_ctxT + ((size_t)bh*DH + dA)*ES;
    float* ctB = g_ctxT + ((size_t)bh*DH + dB)*ES;
#pragma unroll
    for (int j = 0; j < 17; ++j) {
        int m0 = (ntb + j)*8 + 2*q;
        float e0 = (m0   < MM) ? acc[j][0] : 0.f;
        float e1 = (m0+1 < MM) ? acc[j][1] : 0.f;
        float e2 = (m0   < MM) ? acc[j][2] : 0.f;
        float e3 = (m0+1 < MM) ? acc[j][3] : 0.f;
        *(float2*)(ctA + m0) = make_float2(e0, e1);
        *(float2*)(ctB + m0) = make_float2(e2, e3);
    }
    if (t < MM) g_ksumU[(size_t)bh*MM + t] = ks0;
    if (t < 16 && t + 256 < MM) g_ksumU[(size_t)bh*MM + t + 256] = ks1;
    __syncthreads();
    if (t < DH) {
        g_vsum[(size_t)bh*DH + t] = vs_r;
        g_csA[(size_t)bh*DH + t] =
            fmaf(A, csp[0][t] + csp[1][t], (float)MM * RE * vs_r);
    }
    if (t == 0) {
        float s = 0.f;
#pragma unroll
        for (int w = 0; w < 8; ++w) s += redk[w];
        g_kss[bh] = fmaf(A, s, (float)MM * RE * 128.f);
    }
}

// ---------------- k3b_mma: O = Eq @ ctx_scaled, Tn inline ----------------
#define EQ_ST 137
#define K3B_SMEM ((NT*EQ_ST + DH*EQ_ST)*4)

__global__ __launch_bounds__(512, 1)
void k3b_mma()
{
    extern __shared__ float sm[];
    float* Eqs   = sm;
    float* ctxTs = sm + NT*EQ_ST;
    __shared__ float qd_s[NT], Emx_s[NT], Tn_s[NT], cs_s[DH], vs_s[DH];
    __shared__ float ksm_s[ES];
    __shared__ float sA, skss;

    int bh = blockIdx.x, t = threadIdx.x;
    int wid = t >> 5, lane = t & 31;
    int g = lane >> 2, q = lane & 3;
    int mtile = wid >> 1;
    int dbase = (wid & 1)*32;

    if (t == 0) { sA = RATIO * __expf(-dec_f(g_kmax)); skss = g_kss[bh]; }
    if (t < NT) {
        qd_s[t]  = g_qdg[(size_t)bh*NT + t];
        Emx_s[t] = g_Emx[(size_t)bh*NT + t];
        Tn_s[t]  = 0.f;
    }
    if (t < DH) {
        cs_s[t] = g_csA[(size_t)bh*DH + t];
        vs_s[t] = g_vsum[(size_t)bh*DH + t];
    }
    __syncthreads();
    float A = sA;
    for (int i = t; i < ES; i += 512)
        ksm_s[i] = (i < MM) ? fmaf(A, g_ksumU[(size_t)bh*MM + i], RE*128.f) : 0.f;

    const float* Eqg = g_Eq + (size_t)bh*NT*ES;
    const float* ctg = g_ctxT + (size_t)bh*DH*ES;

    float acc[4][4];
#pragma unroll
    for (int j = 0; j < 4; ++j) { acc[j][0]=0.f; acc[j][1]=0.f; acc[j][2]=0.f; acc[j][3]=0.f; }

    for (int c = 0; c < 2; ++c) {
        int m0 = c*136;
        for (int i = t; i < NT*136; i += 512) {
            int r = i / 136, cc = i - r*136;
            Eqs[r*EQ_ST + cc] = Eqg[(size_t)r*ES + m0 + cc];
        }
        for (int i = t; i < DH*136; i += 512) {
            int d = i / 136, cc = i - d*136;
            int mg = m0 + cc;
            float raw = ctg[(size_t)d*ES + mg];
            ctxTs[d*EQ_ST + cc] = (mg < MM) ? fmaf(A, raw, RE*vs_s[d]) : 0.f;
        }
        __syncthreads();

        // Tn partials from smem (fp32)
        for (int j = 0; j < 8; ++j) {
            int n = wid*8 + j;
            const float* er = Eqs + n*EQ_ST;
            float s = 0.f;
            for (int cc = lane; cc < 136; cc += 32)
                s = fmaf(er[cc], ksm_s[m0 + cc], s);
#pragma unroll
            for (int o = 16; o; o >>= 1) s += __shfl_xor_sync(0xffffffffu, s, o);
            if (lane == 0) Tn_s[n] += s;
        }

#pragma unroll
        for (int ks = 0; ks < 17; ++ks) {
            unsigned a0 = __float_as_uint(Eqs[(mtile*16+g)*EQ_ST + ks*8 + q]);
            unsigned a1 = __float_as_uint(Eqs[(mtile*16+g+8)*EQ_ST + ks*8 + q]);
            unsigned a2 = __float_as_uint(Eqs[(mtile*16+g)*EQ_ST + ks*8 + q + 4]);
            unsigned a3 = __float_as_uint(Eqs[(mtile*16+g+8)*EQ_ST + ks*8 + q + 4]);
#pragma unroll
            for (int nt = 0; nt < 4; ++nt) {
                int drow = dbase + nt*8 + g;
                unsigned b0 = __float_as_uint(ctxTs[drow*EQ_ST + ks*8 + q]);
                unsigned b1 = __float_as_uint(ctxTs[drow*EQ_ST + ks*8 + q + 4]);
                mma_tf32(acc[nt][0], acc[nt][1], acc[nt][2], acc[nt][3],
                         a0, a1, a2, a3, b0, b1);
            }
        }
        __syncthreads();
    }

    int rA = mtile*16 + g, rB = rA + 8;
    float rqA = RATIO * __expf(-qd_s[rA]) / Emx_s[rA];
    float rqB = RATIO * __expf(-qd_s[rB]) / Emx_s[rB];
    float kss = skss;
    float invA = 1.0f / fmaf(rqA, Tn_s[rA], RE*kss);
    float invB = 1.0f / fmaf(rqB, Tn_s[rB], RE*kss);
    int b = bh >> 3, h = bh & 7;
    float* oA = g_o + ((size_t)(b*NT + rA))*IN + h*DH;
    float* oB = g_o + ((size_t)(b*NT + rB))*IN + h*DH;
#pragma unroll
    for (int nt = 0; nt < 4; ++nt) {
        int d = dbase + nt*8 + 2*q;
        float2 vA, vB;
        vA.x = fmaf(rqA, acc[nt][0], RE*cs_s[d  ])*invA;
        vA.y = fmaf(rqA, acc[nt][1], RE*cs_s[d+1])*invA;
        vB.x = fmaf(rqB, acc[nt][2], RE*cs_s[d  ])*invB;
        vB.y = fmaf(rqB, acc[nt][3], RE*cs_s[d+1])*invB;
        *(float2*)(oA + d) = vA;
        *(float2*)(oB + d) = vB;
    }
}

// ---------------- k4a_mma ----------------
#define K4A_ST 132
#define K4A_SMEM ((NT*K4A_ST + DH*K4A_ST)*4)

__global__ __launch_bounds__(256, 2)
void k4a_mma(const float* __restrict__ x,
             const float* __restrict__ Wo, const float* __restrict__ bo)
{
    extern __shared__ float sm[];
    float* Os = sm;
    float* Ws = sm + NT*K4A_ST;

    int b = blockIdx.x, t = threadIdx.x;
    int wid = t >> 5, lane = t & 31;
    int g = lane >> 2, q = lane & 3;
    int rA = wid*16 + g, rB = rA + 8;

    float acc[8][4];
#pragma unroll
    for (int j = 0; j < 8; ++j) { acc[j][0]=0.f; acc[j][1]=0.f; acc[j][2]=0.f; acc[j][3]=0.f; }

    const float* ob = g_o + (size_t)b*NT*IN;

    for (int c = 0; c < 4; ++c) {
        int k0 = c*128;
        for (int i = t; i < NT*128; i += 256) {
            int r = i >> 7, kc = i & 127;
            Os[r*K4A_ST + kc] = to_tf32(ob[(size_t)r*IN + k0 + kc]);
        }
        for (int i = t; i < DH*128; i += 256) {
            int k = i >> 6, d = i & 63;
            Ws[d*K4A_ST + k] = to_tf32(Wo[(size_t)(k0+k)*TD + d]);
        }
        __syncthreads();

#pragma unroll
        for (int ks = 0; ks < 16; ++ks) {
            unsigned a0 = __float_as_uint(Os[rA*K4A_ST + ks*8 + q]);
            unsigned a1 = __float_as_uint(Os[rB*K4A_ST + ks*8 + q]);
            unsigned a2 = __float_as_uint(Os[rA*K4A_ST + ks*8 + q + 4]);
            unsigned a3 = __float_as_uint(Os[rB*K4A_ST + ks*8 + q + 4]);
#pragma unroll
            for (int nt = 0; nt < 8; ++nt) {
                int drow = nt*8 + g;
                unsigned b0 = __float_as_uint(Ws[drow*K4A_ST + ks*8 + q]);
                unsigned b1 = __float_as_uint(Ws[drow*K4A_ST + ks*8 + q + 4]);
                mma_tf32(acc[nt][0], acc[nt][1], acc[nt][2], acc[nt][3],
                         a0, a1, a2, a3, b0, b1);
            }
        }
        __syncthreads();
    }

    const float* xb = x + (size_t)b*NT*TD;
    float* tb = g_t + (size_t)b*NT*TD;
#pragma unroll
    for (int nt = 0; nt < 8; ++nt) {
        int d = nt*8 + 2*q;
        float2 bb = *(const float2*)(bo + d);
        float2 xA = *(const float2*)(xb + rA*TD + d);
        float2 xB = *(const float2*)(xb + rB*TD + d);
        *(float2*)(tb + rA*TD + d) =
            make_float2(acc[nt][0] + bb.x + xA.x, acc[nt][1] + bb.y + xA.y);
        *(float2*)(tb + rB*TD + d) =
            make_float2(acc[nt][2] + bb.x + xB.x, acc[nt][3] + bb.y + xB.y);
    }
}

// ---------------- k4b1: LN2 + FF1 (mma) + GELU -> g_ff ----------------
#define FF1_ST 68
#define K4B1_SMEM ((NT*FF1_ST + FH*FF1_ST)*4)  /* 34816 + 69632 */

__global__ __launch_bounds__(256, 2)
void k4b1(const float* __restrict__ g2, const float* __restrict__ b2,
          const float* __restrict__ W1, const float* __restrict__ c1)
{
    extern __shared__ float sm[];
    float* hs = sm;                 // [128][68]
    float* Ws = sm + NT*FF1_ST;     // [256 j][68]

    int b = blockIdx.x, t = threadIdx.x;
    int wid = t >> 5, lane = t & 31;
    int g = lane >> 2, q = lane & 3;
    int rA = wid*16 + g, rB = rA + 8;

    for (int i = t; i < TD*FH; i += 256) {
        int d = i >> 8, j = i & 255;
        Ws[j*FF1_ST + d] = to_tf32(W1[i]);
    }
    if (t < NT) {
        const float* tr = g_t + ((size_t)(b*NT + t))*TD;
        float tv[64];
#pragma unroll
        for (int j = 0; j < 16; ++j) {
            float4 t4 = *(const float4*)(tr + 4*j);
            tv[4*j]=t4.x; tv[4*j+1]=t4.y; tv[4*j+2]=t4.z; tv[4*j+3]=t4.w;
        }
        float mu = 0.f;
#pragma unroll
        for (int d = 0; d < 64; d++) mu += tv[d];
        mu *= (1.f/64.f);
        float var = 0.f;
#pragma unroll
        for (int d = 0; d < 64; d++) { float v = tv[d]-mu; var += v*v; }
        var *= (1.f/64.f);
        float inv = rsqrtf(var + 1e-5f);
#pragma unroll
        for (int d = 0; d < 64; d++)
            hs[t*FF1_ST + d] = to_tf32((tv[d]-mu)*inv*g2[d] + b2[d]);
    }
    __syncthreads();

    unsigned a[8][4];
#pragma unroll
    for (int kc = 0; kc < 8; ++kc) {
        a[kc][0] = __float_as_uint(hs[rA*FF1_ST + kc*8 + q]);
        a[kc][1] = __float_as_uint(hs[rB*FF1_ST + kc*8 + q]);
        a[kc][2] = __float_as_uint(hs[rA*FF1_ST + kc*8 + q + 4]);
        a[kc][3] = __float_as_uint(hs[rB*FF1_ST + kc*8 + q + 4]);
    }

    float* ffb = g_ff + (size_t)b*NT*FH;
    for (int nc = 0; nc < 32; ++nc) {
        float c0=0.f, c1r=0.f, c2=0.f, c3=0.f;
        const float* pb = Ws + (nc*8 + g)*FF1_ST + q;
#pragma unroll
        for (int kc = 0; kc < 8; ++kc) {
            unsigned b0 = __float_as_uint(pb[kc*8]);
            unsigned b1 = __float_as_uint(pb[kc*8 + 4]);
            mma_tf32(c0, c1r, c2, c3,
                     a[kc][0], a[kc][1], a[kc][2], a[kc][3], b0, b1);
        }
        int j0 = nc*8 + 2*q;
        float2 cc = *(const float2*)(c1 + j0);
        float v0 = c0 + cc.x, v1 = c1r + cc.y, v2 = c2 + cc.x, v3 = c3 + cc.y;
        v0 = 0.5f*v0*(1.f + erff(v0*0.70710678f));
        v1 = 0.5f*v1*(1.f + erff(v1*0.70710678f));
        v2 = 0.5f*v2*(1.f + erff(v2*0.70710678f));
        v3 = 0.5f*v3*(1.f + erff(v3*0.70710678f));
        *(float2*)(ffb + (size_t)rA*FH + j0) = make_float2(v0, v1);
        *(float2*)(ffb + (size_t)rB*FH + j0) = make_float2(v2, v3);
    }
}

// ---------------- k4b2: FF2 (mma) + residual + LN3 + pool + head ----------------
#define FF2_ST 132
#define K4B2_SMEM ((NT*FF2_ST + DH*FF2_ST + NT*65)*4)  /* 67584+33792+33280 */

__global__ __launch_bounds__(256, 1)
void k4b2(const float* __restrict__ x,
          const float* __restrict__ W2, const float* __restrict__ c2,
          const float* __restrict__ g3, const float* __restrict__ b3,
          const float* __restrict__ Wf1, const float* __restrict__ bf1,
          const float* __restrict__ Wf2, const float* __restrict__ bf2,
          float* __restrict__ out)
{
    extern __shared__ float sm[];
    float* As = sm;                       // [128][132]
    float* Ws = sm + NT*FF2_ST;           // [64][132]
    float* rs = Ws + DH*FF2_ST;           // [128][65]
    __shared__ float psm[64];
    __shared__ float red[8];

    int b = blockIdx.x, t = threadIdx.x;
    int wid = t >> 5, lane = t & 31;
    int g = lane >> 2, q = lane & 3;
    int rA = wid*16 + g, rB = rA + 8;

    float acc[8][4];
#pragma unroll
    for (int j = 0; j < 8; ++j) { acc[j][0]=0.f; acc[j][1]=0.f; acc[j][2]=0.f; acc[j][3]=0.f; }

    const float* ffb = g_ff + (size_t)b*NT*FH;

    for (int c = 0; c < 2; ++c) {
        int k0 = c*128;
        for (int i = t; i < NT*128; i += 256) {
            int r = i >> 7, kc = i & 127;
            As[r*FF2_ST + kc] = to_tf32(ffb[(size_t)r*FH + k0 + kc]);
        }
        for (int i = t; i < DH*128; i += 256) {
            int kc = i >> 6, d = i & 63;
            Ws[d*FF2_ST + kc] = to_tf32(W2[(size_t)(k0+kc)*TD + d]);
        }
        __syncthreads();

#pragma unroll
        for (int ks = 0; ks < 16; ++ks) {
            unsigned a0 = __float_as_uint(As[rA*FF2_ST + ks*8 + q]);
            unsigned a1 = __float_as_uint(As[rB*FF2_ST + ks*8 + q]);
            unsigned a2 = __float_as_uint(As[rA*FF2_ST + ks*8 + q + 4]);
            unsigned a3 = __float_as_uint(As[rB*FF2_ST + ks*8 + q + 4]);
#pragma unroll
            for (int nt = 0; nt < 8; ++nt) {
                int drow = nt*8 + g;
                unsigned b0 = __float_as_uint(Ws[drow*FF2_ST + ks*8 + q]);
                unsigned b1 = __float_as_uint(Ws[drow*FF2_ST + ks*8 + q + 4]);
                mma_tf32(acc[nt][0], acc[nt][1], acc[nt][2], acc[nt][3],
                         a0, a1, a2, a3, b0, b1);
            }
        }
        __syncthreads();
    }

    // residual: r = ff2 + c2 + t + x
    const float* xb = x + (size_t)b*NT*TD;
    const float* tb = g_t + (size_t)b*NT*TD;
#pragma unroll
    for (int nt = 0; nt < 8; ++nt) {
        int d = nt*8 + 2*q;
        float2 cc = *(const float2*)(c2 + d);
        float2 tA = *(const float2*)(tb + rA*TD + d);
        float2 tB = *(const float2*)(tb + rB*TD + d);
        float2 xA = *(const float2*)(xb + rA*TD + d);
        float2 xB = *(const float2*)(xb + rB*TD + d);
        rs[rA*65 + d]     = acc[nt][0] + cc.x + tA.x + xA.x;
        rs[rA*65 + d + 1] = acc[nt][1] + cc.y + tA.y + xA.y;
        rs[rB*65 + d]     = acc[nt][2] + cc.x + tB.x + xB.x;
        rs[rB*65 + d + 1] = acc[nt][3] + cc.y + tB.y + xB.y;
    }
    __syncthreads();

    if (t < NT) {   // LN3
        float* r = &rs[t*65];
        float mu = 0.f;
#pragma unroll
        for (int d = 0; d < 64; d++) mu += r[d];
        mu *= (1.f/64.f);
        float var = 0.f;
#pragma unroll
        for (int d = 0; d < 64; d++) { float v = r[d]-mu; var += v*v; }
        var *= (1.f/64.f);
        float inv = rsqrtf(var + 1e-5f);
#pragma unroll
        for (int d = 0; d < 64; d++)
            r[d] = (r[d]-mu)*inv*g3[d] + b3[d];
    }
    __syncthreads();

    if (t < TD) {   // mean pool
        float s = 0.f;
        for (int nn = 0; nn < NT; ++nn) s += rs[nn*65 + t];
        psm[t] = s * (1.f/128.f);
    }
    __syncthreads();

    float val = 0.f;
    if (t < 128) {  // head MLP
        float s = bf1[t];
        for (int d = 0; d < TD; ++d)
            s = fmaf(psm[d], Wf1[d*128 + t], s);
        s = fmaxf(s, 0.f);
        val = s * Wf2[t];
    }
#pragma unroll
    for (int o = 16; o; o >>= 1)
        val += __shfl_xor_sync(0xffffffffu, val, o);
    if ((t & 31) == 0) red[t >> 5] = val;
    __syncthreads();
    if (t == 0)
        out[b] = red[0] + red[1] + red[2] + red[3] + bf2[0];
}

// ---------------- launch ----------------
extern "C" void kernel_launch(void* const* d_in, const int* in_sizes, int n_in,
                              void* d_out, int out_size) {
    const float* x    = (const float*)d_in[0];
    const float* g1   = (const float*)d_in[1];
    const float* b1   = (const float*)d_in[2];
    const float* Wq   = (const float*)d_in[3];
    const float* bq   = (const float*)d_in[4];
    const float* Wk   = (const float*)d_in[5];
    const float* bk   = (const float*)d_in[6];
    const float* Wv   = (const float*)d_in[7];
    const float* bv   = (const float*)d_in[8];
    const float* Wo   = (const float*)d_in[9];
    const float* bo   = (const float*)d_in[10];
    const float* proj = (const float*)d_in[11];
    const float* g2   = (const float*)d_in[12];
    const float* b2   = (const float*)d_in[13];
    const float* W1   = (const float*)d_in[14];
    const float* c1   = (const float*)d_in[15];
    const float* W2   = (const float*)d_in[16];
    const float* c2   = (const float*)d_in[17];
    const float* g3   = (const float*)d_in[18];
    const float* b3   = (const float*)d_in[19];
    const float* Wf1  = (const float*)d_in[20];
    const float* bf1  = (const float*)d_in[21];
    const float* Wf2  = (const float*)d_in[22];
    const float* bf2  = (const float*)d_in[23];
    float* out = (float*)d_out;

    cudaFuncSetAttribute(k1_mma,  cudaFuncAttributeMaxDynamicSharedMemorySize, K1_SMEM);
    cudaFuncSetAttribute(kfeat,   cudaFuncAttributeMaxDynamicSharedMemorySize, KF_SMEM);
    cudaFuncSetAttribute(k2b_mma, cudaFuncAttributeMaxDynamicSharedMemorySize, K2B_SMEM);
    cudaFuncSetAttribute(k3b_mma, cudaFuncAttributeMaxDynamicSharedMemorySize, K3B_SMEM);
    cudaFuncSetAttribute(k4a_mma, cudaFuncAttributeMaxDynamicSharedMemorySize, K4A_SMEM);
    cudaFuncSetAttribute(k4b1,    cudaFuncAttributeMaxDynamicSharedMemorySize, K4B1_SMEM);
    cudaFuncSetAttribute(k4b2,    cudaFuncAttributeMaxDynamicSharedMemorySize, K4B2_SMEM);

    k_init<<<1, 1>>>();
    k1_mma<<<dim3(BB, 3), 256, K1_SMEM>>>(x, g1, b1, Wq, bq, Wk, bk, Wv, bv);
    kfeat<<<BB*HH, 256, KF_SMEM>>>(proj);
    k2b_mma<<<BB*HH, 256, K2B_SMEM>>>();
    k3b_mma<<<BB*HH, 512, K3B_SMEM>>>();
    k4a_mma<<<BB, 256, K4A_SMEM>>>(x, Wo, bo);
    k4b1<<<BB, 256, K4B1_SMEM>>>(g2, b2, W1, c1);
    k4b2<<<BB, 256, K4B2_SMEM>>>(x, W2, c2, g3, b3, Wf1, bf1, Wf2, bf2, out);
}